// round 2
// baseline (speedup 1.0000x reference)
#include <cuda_runtime.h>

#define M_GT  512
#define N_CTX 1024
#define FEAT  1024
#define NG    16
#define DK    64
#define MN    (M_GT * N_CTX)   // 524288

// ---------------- device scratch (static globals; no allocation) ------------
__device__ float g_Q[M_GT * FEAT];
__device__ float g_K[N_CTX * FEAT];
__device__ float g_U[M_GT * FEAT];
__device__ float g_V[N_CTX * FEAT];
__device__ float g_S[NG * MN];    // scores  (G, M, N)
__device__ float g_L1[NG * MN];   // logits/weights gt  (G, M, N)
__device__ float g_L2[NG * MN];   // logits/weights ctx (G, N, M)

// 1000^(-j/8)
__constant__ float c_invdim[8] = {
    1.0f, 0.4216965034f, 0.1778279410f, 0.0749894209f,
    0.0316227766f, 0.0133352143f, 0.0056234133f, 0.0023713737f
};

// ---------------------------------------------------------------------------
// Fused projection GEMM: C = A @ W^T (+bias). 128x128x16 tiles, 256 thr, 8x8.
//   z=0: Q = feat     @ w_fc_gt^T  + b_fc_gt
//   z=1: K = ctx_feat @ w_fc_ctx^T + b_fc_ctx
//   z=2: U = feat     @ w_conv^T
//   z=3: V = ctx_feat @ w_conv^T
// ---------------------------------------------------------------------------
__global__ __launch_bounds__(256) void proj_gemm(
    const float* __restrict__ feat, const float* __restrict__ ctx_feat,
    const float* __restrict__ w_gt, const float* __restrict__ b_gt,
    const float* __restrict__ w_ctx, const float* __restrict__ b_ctx,
    const float* __restrict__ w_conv)
{
    const float* A; const float* W; const float* bias; float* C; int Mrows;
    switch (blockIdx.z) {
    case 0:  A = feat;     W = w_gt;   bias = b_gt;  C = g_Q; Mrows = M_GT;  break;
    case 1:  A = ctx_feat; W = w_ctx;  bias = b_ctx; C = g_K; Mrows = N_CTX; break;
    case 2:  A = feat;     W = w_conv; bias = 0;     C = g_U; Mrows = M_GT;  break;
    default: A = ctx_feat; W = w_conv; bias = 0;     C = g_V; Mrows = N_CTX; break;
    }
    int bm = blockIdx.y * 128;
    if (bm >= Mrows) return;
    int bn = blockIdx.x * 128;

    __shared__ float As[16][132];   // [k][m], stride 132 keeps 16B align, 2-way store conflicts
    __shared__ float Ws[16][132];

    int tid = threadIdx.x;
    int tx = tid & 15, ty = tid >> 4;
    int lr = tid >> 2;              // 0..63
    int lc = (tid & 3) << 2;        // 0,4,8,12

    float acc[8][8];
    #pragma unroll
    for (int i = 0; i < 8; i++)
        #pragma unroll
        for (int j = 0; j < 8; j++) acc[i][j] = 0.0f;

    const float* Ap = A + (size_t)(bm + lr) * FEAT + lc;
    const float* Wp = W + (size_t)(bn + lr) * FEAT + lc;

    for (int k0 = 0; k0 < FEAT; k0 += 16) {
        float4 a0 = *(const float4*)(Ap + k0);
        float4 a1 = *(const float4*)(Ap + 64 * FEAT + k0);
        float4 w0 = *(const float4*)(Wp + k0);
        float4 w1 = *(const float4*)(Wp + 64 * FEAT + k0);
        As[lc+0][lr]    = a0.x; As[lc+1][lr]    = a0.y; As[lc+2][lr]    = a0.z; As[lc+3][lr]    = a0.w;
        As[lc+0][lr+64] = a1.x; As[lc+1][lr+64] = a1.y; As[lc+2][lr+64] = a1.z; As[lc+3][lr+64] = a1.w;
        Ws[lc+0][lr]    = w0.x; Ws[lc+1][lr]    = w0.y; Ws[lc+2][lr]    = w0.z; Ws[lc+3][lr]    = w0.w;
        Ws[lc+0][lr+64] = w1.x; Ws[lc+1][lr+64] = w1.y; Ws[lc+2][lr+64] = w1.z; Ws[lc+3][lr+64] = w1.w;
        __syncthreads();
        #pragma unroll
        for (int kk = 0; kk < 16; kk++) {
            float a[8], b[8];
            *(float4*)&a[0] = *(const float4*)&As[kk][ty * 8];
            *(float4*)&a[4] = *(const float4*)&As[kk][ty * 8 + 4];
            *(float4*)&b[0] = *(const float4*)&Ws[kk][tx * 8];
            *(float4*)&b[4] = *(const float4*)&Ws[kk][tx * 8 + 4];
            #pragma unroll
            for (int i = 0; i < 8; i++)
                #pragma unroll
                for (int j = 0; j < 8; j++)
                    acc[i][j] += a[i] * b[j];
        }
        __syncthreads();
    }

    float bv[8];
    #pragma unroll
    for (int j = 0; j < 8; j++) bv[j] = bias ? bias[bn + tx * 8 + j] : 0.0f;

    #pragma unroll
    for (int i = 0; i < 8; i++) {
        int row = bm + ty * 8 + i;
        int col = bn + tx * 8;
        float4 o0, o1;
        o0.x = acc[i][0] + bv[0]; o0.y = acc[i][1] + bv[1];
        o0.z = acc[i][2] + bv[2]; o0.w = acc[i][3] + bv[3];
        o1.x = acc[i][4] + bv[4]; o1.y = acc[i][5] + bv[5];
        o1.z = acc[i][6] + bv[6]; o1.w = acc[i][7] + bv[7];
        *(float4*)(C + (size_t)row * FEAT + col)     = o0;
        *(float4*)(C + (size_t)row * FEAT + col + 4) = o1;
    }
}

// ---------------------------------------------------------------------------
// scores[g,m,n] = (1/8) * sum_d Q[m, g*64+d] * K[n, g*64+d]
// Batched over g. 128x128 tiles, K=64.
// ---------------------------------------------------------------------------
__global__ __launch_bounds__(256) void score_gemm()
{
    int g = blockIdx.z;
    const float* A = g_Q + g * DK;
    const float* B = g_K + g * DK;
    float* C = g_S + (size_t)g * MN;
    int bm = blockIdx.y * 128;
    int bn = blockIdx.x * 128;

    __shared__ float As[16][132];
    __shared__ float Ws[16][132];

    int tid = threadIdx.x;
    int tx = tid & 15, ty = tid >> 4;
    int lr = tid >> 2;
    int lc = (tid & 3) << 2;

    float acc[8][8];
    #pragma unroll
    for (int i = 0; i < 8; i++)
        #pragma unroll
        for (int j = 0; j < 8; j++) acc[i][j] = 0.0f;

    const float* Ap = A + (size_t)(bm + lr) * FEAT + lc;
    const float* Wp = B + (size_t)(bn + lr) * FEAT + lc;

    for (int k0 = 0; k0 < DK; k0 += 16) {
        float4 a0 = *(const float4*)(Ap + k0);
        float4 a1 = *(const float4*)(Ap + 64 * FEAT + k0);
        float4 w0 = *(const float4*)(Wp + k0);
        float4 w1 = *(const float4*)(Wp + 64 * FEAT + k0);
        As[lc+0][lr]    = a0.x; As[lc+1][lr]    = a0.y; As[lc+2][lr]    = a0.z; As[lc+3][lr]    = a0.w;
        As[lc+0][lr+64] = a1.x; As[lc+1][lr+64] = a1.y; As[lc+2][lr+64] = a1.z; As[lc+3][lr+64] = a1.w;
        Ws[lc+0][lr]    = w0.x; Ws[lc+1][lr]    = w0.y; Ws[lc+2][lr]    = w0.z; Ws[lc+3][lr]    = w0.w;
        Ws[lc+0][lr+64] = w1.x; Ws[lc+1][lr+64] = w1.y; Ws[lc+2][lr+64] = w1.z; Ws[lc+3][lr+64] = w1.w;
        __syncthreads();
        #pragma unroll
        for (int kk = 0; kk < 16; kk++) {
            float a[8], b[8];
            *(float4*)&a[0] = *(const float4*)&As[kk][ty * 8];
            *(float4*)&a[4] = *(const float4*)&As[kk][ty * 8 + 4];
            *(float4*)&b[0] = *(const float4*)&Ws[kk][tx * 8];
            *(float4*)&b[4] = *(const float4*)&Ws[kk][tx * 8 + 4];
            #pragma unroll
            for (int i = 0; i < 8; i++)
                #pragma unroll
                for (int j = 0; j < 8; j++)
                    acc[i][j] += a[i] * b[j];
        }
        __syncthreads();
    }

    #pragma unroll
    for (int i = 0; i < 8; i++) {
        int row = bm + ty * 8 + i;
        int col = bn + tx * 8;
        float4 o0, o1;
        o0.x = acc[i][0] * 0.125f; o0.y = acc[i][1] * 0.125f;
        o0.z = acc[i][2] * 0.125f; o0.w = acc[i][3] * 0.125f;
        o1.x = acc[i][4] * 0.125f; o1.y = acc[i][5] * 0.125f;
        o1.z = acc[i][6] * 0.125f; o1.w = acc[i][7] * 0.125f;
        *(float4*)(C + (size_t)row * N_CTX + col)     = o0;
        *(float4*)(C + (size_t)row * N_CTX + col + 4) = o1;
    }
}

// ---------------------------------------------------------------------------
// Position embedding + relu + pos-linear + log-clip + add scores, fused.
// One thread per (r, c) pair; 16 group logits each.
//   L[g, r, c] = log(max(pe(r,c) . w_pos[g] + b_pos[g], 1e-6)) + scores[g, sidx]
// ---------------------------------------------------------------------------
__global__ __launch_bounds__(256) void pos_logit(
    const float4* __restrict__ boxA, const float4* __restrict__ boxB,
    const float* __restrict__ w_pos, const float* __restrict__ b_pos,
    const float* __restrict__ scores, int srow, int scol,
    float* __restrict__ L, int Ccols)
{
    __shared__ float wp[NG * 64];
    __shared__ float bp[NG];
    int tid = threadIdx.x;
    for (int i = tid; i < NG * 64; i += 256) wp[i] = w_pos[i];
    if (tid < NG) bp[tid] = b_pos[tid];
    __syncthreads();

    int r = blockIdx.y;
    int c = blockIdx.x * 256 + tid;

    float4 A  = boxA[r];
    float4 Bx = boxB[c];
    float bw  = A.z - A.x + 1.0f,  bh  = A.w - A.y + 1.0f;
    float cx  = 0.5f * (A.x + A.z), cy = 0.5f * (A.y + A.w);
    float cbw = Bx.z - Bx.x + 1.0f, cbh = Bx.w - Bx.y + 1.0f;
    float ccx = 0.5f * (Bx.x + Bx.z), ccy = 0.5f * (Bx.y + Bx.w);

    float pos[4];
    pos[0] = __logf(fmaxf(fabsf((cx - ccx) / bw), 1e-3f));
    pos[1] = __logf(fmaxf(fabsf((cy - ccy) / bh), 1e-3f));
    pos[2] = __logf(cbw / bw);
    pos[3] = __logf(cbh / bh);

    float acc[NG];
    #pragma unroll
    for (int g = 0; g < NG; g++) acc[g] = 0.0f;

    #pragma unroll
    for (int p = 0; p < 4; p++) {
        float base = 100.0f * pos[p];
        #pragma unroll
        for (int j = 0; j < 8; j++) {
            float s, co;
            __sincosf(base * c_invdim[j], &s, &co);
            s  = fmaxf(s, 0.0f);
            co = fmaxf(co, 0.0f);
            #pragma unroll
            for (int g = 0; g < NG; g++)
                acc[g] += s * wp[g * 64 + p * 16 + j] + co * wp[g * 64 + p * 16 + 8 + j];
        }
    }

    size_t oidx = (size_t)r * Ccols + c;
    size_t sidx = (size_t)r * srow + (size_t)c * scol;
    #pragma unroll
    for (int g = 0; g < NG; g++) {
        float v = fmaxf(acc[g] + bp[g], 1e-6f);
        L[(size_t)g * MN + oidx] = __logf(v) + scores[(size_t)g * MN + sidx];
    }
}

// ---------------------------------------------------------------------------
// In-place row softmax. grid = nrows, block = 256, rowlen in {512, 1024}.
// ---------------------------------------------------------------------------
__global__ __launch_bounds__(256) void softmax_rows(float* __restrict__ buf, int rowlen)
{
    float* row = buf + (size_t)blockIdx.x * rowlen;
    int tid = threadIdx.x;
    int n = rowlen >> 8;                 // 2 or 4 chunks
    float v[4];
    float m = -3.4e38f;
    #pragma unroll
    for (int i = 0; i < 4; i++)
        if (i < n) { v[i] = row[tid + (i << 8)]; m = fmaxf(m, v[i]); }

    __shared__ float sm[8];
    #pragma unroll
    for (int o = 16; o; o >>= 1) m = fmaxf(m, __shfl_xor_sync(0xffffffffu, m, o));
    if ((tid & 31) == 0) sm[tid >> 5] = m;
    __syncthreads();
    if (tid == 0) {
        float t = sm[0];
        #pragma unroll
        for (int i = 1; i < 8; i++) t = fmaxf(t, sm[i]);
        sm[0] = t;
    }
    __syncthreads();
    m = sm[0];

    float s = 0.0f;
    #pragma unroll
    for (int i = 0; i < 4; i++)
        if (i < n) { v[i] = __expf(v[i] - m); s += v[i]; }

    __syncthreads();   // protect sm reuse
    #pragma unroll
    for (int o = 16; o; o >>= 1) s += __shfl_xor_sync(0xffffffffu, s, o);
    if ((tid & 31) == 0) sm[tid >> 5] = s;
    __syncthreads();
    if (tid == 0) {
        float t = 0.0f;
        #pragma unroll
        for (int i = 0; i < 8; i++) t += sm[i];
        sm[0] = t;
    }
    __syncthreads();
    float inv = 1.0f / sm[0];
    #pragma unroll
    for (int i = 0; i < 4; i++)
        if (i < n) row[tid + (i << 8)] = v[i] * inv;
}

// ---------------------------------------------------------------------------
// Attention output GEMM, batched over z (0..15 gt, 16..31 ctx):
//   gt : out_gt[m, g*64+o]  = sum_n w1[g,m,n] * V[n, g*64+o] + b_conv
//   ctx: out_ctx[n, g*64+o] = sum_m w2[g,n,m] * U[m, g*64+o] + b_conv
// 128x64 tiles, 256 threads, per-thread 8x4.
// ---------------------------------------------------------------------------
__global__ __launch_bounds__(256) void attn_gemm(
    const float* __restrict__ b_conv, float* __restrict__ out_gt,
    float* __restrict__ out_ctx)
{
    int z = blockIdx.z;
    int g = z & 15;
    bool gt = z < 16;
    const float* A = gt ? (g_L1 + (size_t)g * MN) : (g_L2 + (size_t)g * MN);
    const float* B = gt ? g_V : g_U;
    float* C   = gt ? out_gt : out_ctx;
    int Mrows  = gt ? M_GT : N_CTX;
    int Ktot   = gt ? N_CTX : M_GT;
    int bm = blockIdx.y * 128;
    if (bm >= Mrows) return;
    int coloff = g * DK;

    __shared__ float As[16][132];
    __shared__ float Bs[16][68];

    int tid = threadIdx.x;
    int tx = tid & 15, ty = tid >> 4;
    int lr = tid >> 2, lc = (tid & 3) << 2;
    int br = tid >> 4, bc = (tid & 15) << 2;

    float acc[8][4];
    #pragma unroll
    for (int i = 0; i < 8; i++)
        #pragma unroll
        for (int j = 0; j < 4; j++) acc[i][j] = 0.0f;

    const float* Ap = A + (size_t)(bm + lr) * Ktot + lc;
    const float* Bp = B + (size_t)br * FEAT + coloff + bc;

    for (int k0 = 0; k0 < Ktot; k0 += 16) {
        float4 a0 = *(const float4*)(Ap + k0);
        float4 a1 = *(const float4*)(Ap + (size_t)64 * Ktot + k0);
        float4 bv = *(const float4*)(Bp + (size_t)k0 * FEAT);
        As[lc+0][lr]    = a0.x; As[lc+1][lr]    = a0.y; As[lc+2][lr]    = a0.z; As[lc+3][lr]    = a0.w;
        As[lc+0][lr+64] = a1.x; As[lc+1][lr+64] = a1.y; As[lc+2][lr+64] = a1.z; As[lc+3][lr+64] = a1.w;
        *(float4*)&Bs[br][bc] = bv;
        __syncthreads();
        #pragma unroll
        for (int kk = 0; kk < 16; kk++) {
            float a[8];
            *(float4*)&a[0] = *(const float4*)&As[kk][ty * 8];
            *(float4*)&a[4] = *(const float4*)&As[kk][ty * 8 + 4];
            float4 b4 = *(const float4*)&Bs[kk][tx * 4];
            #pragma unroll
            for (int i = 0; i < 8; i++) {
                acc[i][0] += a[i] * b4.x;
                acc[i][1] += a[i] * b4.y;
                acc[i][2] += a[i] * b4.z;
                acc[i][3] += a[i] * b4.w;
            }
        }
        __syncthreads();
    }

    float bb0 = b_conv[coloff + tx * 4 + 0];
    float bb1 = b_conv[coloff + tx * 4 + 1];
    float bb2 = b_conv[coloff + tx * 4 + 2];
    float bb3 = b_conv[coloff + tx * 4 + 3];

    #pragma unroll
    for (int i = 0; i < 8; i++) {
        int row = bm + ty * 8 + i;
        float4 o;
        o.x = acc[i][0] + bb0; o.y = acc[i][1] + bb1;
        o.z = acc[i][2] + bb2; o.w = acc[i][3] + bb3;
        *(float4*)(C + (size_t)row * FEAT + coloff + tx * 4) = o;
    }
}

// ---------------------------------------------------------------------------
extern "C" void kernel_launch(void* const* d_in, const int* in_sizes, int n_in,
                              void* d_out, int out_size)
{
    (void)in_sizes; (void)n_in; (void)out_size;
    const float* feat      = (const float*)d_in[0];
    const float* ctx_feat  = (const float*)d_in[1];
    const float* box       = (const float*)d_in[2];
    const float* ctx_box   = (const float*)d_in[3];
    const float* w_fc_gt   = (const float*)d_in[4];
    const float* b_fc_gt   = (const float*)d_in[5];
    const float* w_fc_ctx  = (const float*)d_in[6];
    const float* b_fc_ctx  = (const float*)d_in[7];
    const float* w_pos_gt  = (const float*)d_in[8];
    const float* b_pos_gt  = (const float*)d_in[9];
    const float* w_pos_ctx = (const float*)d_in[10];
    const float* b_pos_ctx = (const float*)d_in[11];
    const float* w_conv    = (const float*)d_in[12];
    const float* b_conv    = (const float*)d_in[13];

    float* out = (float*)d_out;
    float* out_gt  = out;
    float* out_ctx = out + (size_t)M_GT * FEAT;

    float *S, *L1, *L2;
    cudaGetSymbolAddress((void**)&S,  g_S);
    cudaGetSymbolAddress((void**)&L1, g_L1);
    cudaGetSymbolAddress((void**)&L2, g_L2);

    // 1) Q, K, U, V projections (fused launch)
    proj_gemm<<<dim3(8, 8, 4), 256>>>(feat, ctx_feat, w_fc_gt, b_fc_gt,
                                      w_fc_ctx, b_fc_ctx, w_conv);
    // 2) scores (G, M, N)
    score_gemm<<<dim3(8, 4, 16), 256>>>();
    // 3) fused position-embedding logits
    pos_logit<<<dim3(4, M_GT), 256>>>((const float4*)box, (const float4*)ctx_box,
                                      w_pos_gt, b_pos_gt, S, N_CTX, 1, L1, N_CTX);
    pos_logit<<<dim3(2, N_CTX), 256>>>((const float4*)ctx_box, (const float4*)box,
                                       w_pos_ctx, b_pos_ctx, S, 1, N_CTX, L2, M_GT);
    // 4) softmax rows
    softmax_rows<<<NG * M_GT,  256>>>(L1, N_CTX);
    softmax_rows<<<NG * N_CTX, 256>>>(L2, M_GT);
    // 5) attention output
    attn_gemm<<<dim3(1, 8, 32), 256>>>(b_conv, out_gt, out_ctx);
}

// round 5
// speedup vs baseline: 2.0262x; 2.0262x over previous
#include <cuda_runtime.h>
#include <cstdint>

#define M_GT  512
#define N_CTX 1024
#define FEAT  1024
#define NG    16
#define DK    64
#define MN    (M_GT * N_CTX)   // 524288

// ---------------- device scratch (static globals; no allocation) ------------
__device__ float g_Q [M_GT * FEAT];
__device__ float g_K [N_CTX * FEAT];
__device__ float g_Ut[FEAT * M_GT];    // Ut[o][m] = (feat @ w_conv^T)^T
__device__ float g_Vt[FEAT * N_CTX];   // Vt[o][n] = (ctx  @ w_conv^T)^T
__device__ float g_S [NG * MN];        // scores  (G, M, N)
__device__ float g_L1[NG * MN];        // logits/weights gt  (G, M, N)
__device__ float g_L2[NG * MN];        // logits/weights ctx (G, N, M)

// 1000^(-j/8)
__constant__ float c_invdim[8] = {
    1.0f, 0.4216965034f, 0.1778279410f, 0.0749894209f,
    0.0316227766f, 0.0133352143f, 0.0056234133f, 0.0023713737f
};

// ======================= mma.sync tf32 helpers ==============================
__device__ __forceinline__ uint32_t f2tf(float x) {
    uint32_t r;
    asm("cvt.rna.tf32.f32 %0, %1;" : "=r"(r) : "f"(x));
    return r;
}

__device__ __forceinline__ void mma8(float* c, const uint32_t* a, const uint32_t* b) {
    asm volatile(
        "mma.sync.aligned.m16n8k8.row.col.f32.tf32.tf32.f32 "
        "{%0,%1,%2,%3}, {%4,%5,%6,%7}, {%8,%9}, {%0,%1,%2,%3};"
        : "+f"(c[0]), "+f"(c[1]), "+f"(c[2]), "+f"(c[3])
        : "r"(a[0]), "r"(a[1]), "r"(a[2]), "r"(a[3]), "r"(b[0]), "r"(b[1]));
}

#define LDP 36   // smem row pitch (floats); 36*4=144 bytes, 16B-aligned rows

// Stage ROWS x 32 fp32 chunk -> tf32 smem [ROWS][LDP]
template <int ROWS>
__device__ __forceinline__ void stage(const float* __restrict__ g, int ld,
                                      uint32_t* __restrict__ sm, int tid)
{
#pragma unroll
    for (int i = 0; i < ROWS / 32; i++) {
        int idx = tid + i * 256;
        int r = idx >> 3, c = (idx & 7) << 2;
        float4 v = *(const float4*)(g + (size_t)r * ld + c);
        uint4 t;
        t.x = f2tf(v.x); t.y = f2tf(v.y); t.z = f2tf(v.z); t.w = f2tf(v.w);
        *(uint4*)(sm + r * LDP + c) = t;
    }
}

// ---------------------------------------------------------------------------
// proj_mma: C = A @ W^T (+bias along N). 128x128 tiles, K=1024.
//   z=0: Q  = feat    @ w_fc_gt^T  + b   (512 x1024)
//   z=1: K  = ctx     @ w_fc_ctx^T + b   (1024x1024)
//   z=2: Ut = w_conv  @ feat^T           (1024x 512)
//   z=3: Vt = w_conv  @ ctx^T            (1024x1024)
// ---------------------------------------------------------------------------
__global__ __launch_bounds__(256, 2) void proj_mma(
    const float* __restrict__ feat, const float* __restrict__ ctx_feat,
    const float* __restrict__ w_gt, const float* __restrict__ b_gt,
    const float* __restrict__ w_ctx, const float* __restrict__ b_ctx,
    const float* __restrict__ w_conv)
{
    const float* A; const float* W; const float* bias; float* C;
    int Mrows, Ncols;
    switch (blockIdx.z) {
    case 0:  A = feat;   W = w_gt;     bias = b_gt;  C = g_Q;  Mrows = M_GT;  Ncols = FEAT;  break;
    case 1:  A = ctx_feat; W = w_ctx;  bias = b_ctx; C = g_K;  Mrows = N_CTX; Ncols = FEAT;  break;
    case 2:  A = w_conv; W = feat;     bias = 0;     C = g_Ut; Mrows = FEAT;  Ncols = M_GT;  break;
    default: A = w_conv; W = ctx_feat; bias = 0;     C = g_Vt; Mrows = FEAT;  Ncols = N_CTX; break;
    }
    int bm = blockIdx.y * 128, bn = blockIdx.x * 128;
    if (bm >= Mrows || bn >= Ncols) return;

    __shared__ uint32_t As[128 * LDP];
    __shared__ uint32_t Bs[128 * LDP];

    int tid = threadIdx.x, wid = tid >> 5, lane = tid & 31;
    int g4 = lane >> 2, tig = lane & 3;
    int wm = (wid & 1) * 64, wn = (wid >> 1) * 32;

    float acc[4][4][4];
#pragma unroll
    for (int i = 0; i < 4; i++)
#pragma unroll
        for (int j = 0; j < 4; j++)
#pragma unroll
            for (int q = 0; q < 4; q++) acc[i][j][q] = 0.0f;

    const float* Ab = A + (size_t)bm * FEAT;
    const float* Wb = W + (size_t)bn * FEAT;

    for (int ch = 0; ch < FEAT / 32; ch++) {
        stage<128>(Ab + ch * 32, FEAT, As, tid);
        stage<128>(Wb + ch * 32, FEAT, Bs, tid);
        __syncthreads();
#pragma unroll
        for (int kk = 0; kk < 4; kk++) {
            int k0 = kk * 8 + tig;
            uint32_t bf[4][2];
#pragma unroll
            for (int j = 0; j < 4; j++) {
                int rn = (wn + j * 8 + g4) * LDP;
                bf[j][0] = Bs[rn + k0];
                bf[j][1] = Bs[rn + k0 + 4];
            }
#pragma unroll
            for (int i = 0; i < 4; i++) {
                int r0 = (wm + i * 16 + g4) * LDP;
                uint32_t af[4];
                af[0] = As[r0 + k0];
                af[1] = As[r0 + 8 * LDP + k0];
                af[2] = As[r0 + k0 + 4];
                af[3] = As[r0 + 8 * LDP + k0 + 4];
#pragma unroll
                for (int j = 0; j < 4; j++) mma8(acc[i][j], af, bf[j]);
            }
        }
        __syncthreads();
    }

#pragma unroll
    for (int i = 0; i < 4; i++) {
        int row = bm + wm + i * 16 + g4;
#pragma unroll
        for (int j = 0; j < 4; j++) {
            int col = bn + wn + j * 8 + 2 * tig;
            float b0 = bias ? bias[col] : 0.0f;
            float b1 = bias ? bias[col + 1] : 0.0f;
            float2 o0, o1;
            o0.x = acc[i][j][0] + b0; o0.y = acc[i][j][1] + b1;
            o1.x = acc[i][j][2] + b0; o1.y = acc[i][j][3] + b1;
            *(float2*)(C + (size_t)row * Ncols + col)       = o0;
            *(float2*)(C + (size_t)(row + 8) * Ncols + col) = o1;
        }
    }
}

// ---------------------------------------------------------------------------
// scores_mma: S[g,m,n] = 0.125 * sum_d Q[m,g*64+d]*K[n,g*64+d]
// ---------------------------------------------------------------------------
__global__ __launch_bounds__(256, 2) void scores_mma()
{
    int g = blockIdx.z;
    int bm = blockIdx.y * 128, bn = blockIdx.x * 128;
    const float* A = g_Q + (size_t)bm * FEAT + g * DK;
    const float* B = g_K + (size_t)bn * FEAT + g * DK;
    float* C = g_S + (size_t)g * MN;

    __shared__ uint32_t As[128 * LDP];
    __shared__ uint32_t Bs[128 * LDP];

    int tid = threadIdx.x, wid = tid >> 5, lane = tid & 31;
    int g4 = lane >> 2, tig = lane & 3;
    int wm = (wid & 1) * 64, wn = (wid >> 1) * 32;

    float acc[4][4][4];
#pragma unroll
    for (int i = 0; i < 4; i++)
#pragma unroll
        for (int j = 0; j < 4; j++)
#pragma unroll
            for (int q = 0; q < 4; q++) acc[i][j][q] = 0.0f;

    for (int ch = 0; ch < 2; ch++) {
        stage<128>(A + ch * 32, FEAT, As, tid);
        stage<128>(B + ch * 32, FEAT, Bs, tid);
        __syncthreads();
#pragma unroll
        for (int kk = 0; kk < 4; kk++) {
            int k0 = kk * 8 + tig;
            uint32_t bf[4][2];
#pragma unroll
            for (int j = 0; j < 4; j++) {
                int rn = (wn + j * 8 + g4) * LDP;
                bf[j][0] = Bs[rn + k0];
                bf[j][1] = Bs[rn + k0 + 4];
            }
#pragma unroll
            for (int i = 0; i < 4; i++) {
                int r0 = (wm + i * 16 + g4) * LDP;
                uint32_t af[4];
                af[0] = As[r0 + k0];
                af[1] = As[r0 + 8 * LDP + k0];
                af[2] = As[r0 + k0 + 4];
                af[3] = As[r0 + 8 * LDP + k0 + 4];
#pragma unroll
                for (int j = 0; j < 4; j++) mma8(acc[i][j], af, bf[j]);
            }
        }
        __syncthreads();
    }

#pragma unroll
    for (int i = 0; i < 4; i++) {
        int row = bm + wm + i * 16 + g4;
#pragma unroll
        for (int j = 0; j < 4; j++) {
            int col = bn + wn + j * 8 + 2 * tig;
            float2 o0, o1;
            o0.x = acc[i][j][0] * 0.125f; o0.y = acc[i][j][1] * 0.125f;
            o1.x = acc[i][j][2] * 0.125f; o1.y = acc[i][j][3] * 0.125f;
            *(float2*)(C + (size_t)row * N_CTX + col)       = o0;
            *(float2*)(C + (size_t)(row + 8) * N_CTX + col) = o1;
        }
    }
}

// ---------------------------------------------------------------------------
// attn_mma: z 0..15 gt: out_gt[m, g*64+o]  = sum_n L1[g,m,n]*Vt[g*64+o][n] + b
//           z 16..31  : out_ctx[n, g*64+o] = sum_m L2[g,n,m]*Ut[g*64+o][m] + b
// 128(M) x 64(N) tiles. Warp tile 64x16.
// ---------------------------------------------------------------------------
__global__ __launch_bounds__(256, 2) void attn_mma(
    const float* __restrict__ b_conv, float* __restrict__ out_gt,
    float* __restrict__ out_ctx)
{
    int z = blockIdx.z;
    int g = z & 15;
    bool gt = z < 16;
    const float* A = gt ? g_L1 + (size_t)g * MN : g_L2 + (size_t)g * MN;
    const float* B = gt ? g_Vt + (size_t)(g * DK) * N_CTX
                        : g_Ut + (size_t)(g * DK) * M_GT;
    float* C  = gt ? out_gt : out_ctx;
    int Mrows = gt ? M_GT : N_CTX;
    int Ktot  = gt ? N_CTX : M_GT;
    int bm = blockIdx.y * 128;
    if (bm >= Mrows) return;

    __shared__ uint32_t As[128 * LDP];
    __shared__ uint32_t Bs[64 * LDP];

    int tid = threadIdx.x, wid = tid >> 5, lane = tid & 31;
    int g4 = lane >> 2, tig = lane & 3;
    int wm = (wid & 1) * 64, wn = (wid >> 1) * 16;

    float acc[4][2][4];
#pragma unroll
    for (int i = 0; i < 4; i++)
#pragma unroll
        for (int j = 0; j < 2; j++)
#pragma unroll
            for (int q = 0; q < 4; q++) acc[i][j][q] = 0.0f;

    const float* Ab = A + (size_t)bm * Ktot;

    for (int ch = 0; ch < Ktot / 32; ch++) {
        stage<128>(Ab + ch * 32, Ktot, As, tid);
        stage<64> (B  + ch * 32, Ktot, Bs, tid);
        __syncthreads();
#pragma unroll
        for (int kk = 0; kk < 4; kk++) {
            int k0 = kk * 8 + tig;
            uint32_t bf[2][2];
#pragma unroll
            for (int j = 0; j < 2; j++) {
                int rn = (wn + j * 8 + g4) * LDP;
                bf[j][0] = Bs[rn + k0];
                bf[j][1] = Bs[rn + k0 + 4];
            }
#pragma unroll
            for (int i = 0; i < 4; i++) {
                int r0 = (wm + i * 16 + g4) * LDP;
                uint32_t af[4];
                af[0] = As[r0 + k0];
                af[1] = As[r0 + 8 * LDP + k0];
                af[2] = As[r0 + k0 + 4];
                af[3] = As[r0 + 8 * LDP + k0 + 4];
#pragma unroll
                for (int j = 0; j < 2; j++) mma8(acc[i][j], af, bf[j]);
            }
        }
        __syncthreads();
    }

#pragma unroll
    for (int i = 0; i < 4; i++) {
        int row = bm + wm + i * 16 + g4;
#pragma unroll
        for (int j = 0; j < 2; j++) {
            int col = g * DK + wn + j * 8 + 2 * tig;
            float b0 = b_conv[col], b1 = b_conv[col + 1];
            float2 o0, o1;
            o0.x = acc[i][j][0] + b0; o0.y = acc[i][j][1] + b1;
            o1.x = acc[i][j][2] + b0; o1.y = acc[i][j][3] + b1;
            *(float2*)(C + (size_t)row * FEAT + col)       = o0;
            *(float2*)(C + (size_t)(row + 8) * FEAT + col) = o1;
        }
    }
}

// ---------------------------------------------------------------------------
// pos_logit v2: 2 columns/thread, packed f32x2 FMA, dup weights in smem.
// ---------------------------------------------------------------------------
__global__ __launch_bounds__(256) void pos_logit2(
    const float4* __restrict__ boxA, const float4* __restrict__ boxB,
    const float* __restrict__ w_pos, const float* __restrict__ b_pos,
    const float* __restrict__ scores, int srow, int scol,
    float* __restrict__ L, int Ccols)
{
    __shared__ __align__(16) float wq[512 * 4];   // [pj*16+g] = {ws,ws,wc,wc}
    __shared__ float bp[NG];
    int tid = threadIdx.x;
    for (int i = tid; i < 512; i += 256) {
        int pj = i >> 4, g = i & 15;
        int p = pj >> 3, j = pj & 7;
        float ws = w_pos[g * 64 + p * 16 + j];
        float wc = w_pos[g * 64 + p * 16 + 8 + j];
        wq[i * 4 + 0] = ws; wq[i * 4 + 1] = ws;
        wq[i * 4 + 2] = wc; wq[i * 4 + 3] = wc;
    }
    if (tid < NG) bp[tid] = b_pos[tid];
    __syncthreads();

    int r = blockIdx.y;
    int c0 = (blockIdx.x * 256 + tid) * 2;

    float4 A  = boxA[r];
    float4 Ba = boxB[c0];
    float4 Bb = boxB[c0 + 1];
    float bw = A.z - A.x + 1.0f, bh = A.w - A.y + 1.0f;
    float cx = 0.5f * (A.x + A.z), cy = 0.5f * (A.y + A.w);

    float pa[4], pb[4];
    pa[0] = __logf(fmaxf(fabsf((cx - 0.5f * (Ba.x + Ba.z)) / bw), 1e-3f));
    pa[1] = __logf(fmaxf(fabsf((cy - 0.5f * (Ba.y + Ba.w)) / bh), 1e-3f));
    pa[2] = __logf((Ba.z - Ba.x + 1.0f) / bw);
    pa[3] = __logf((Ba.w - Ba.y + 1.0f) / bh);
    pb[0] = __logf(fmaxf(fabsf((cx - 0.5f * (Bb.x + Bb.z)) / bw), 1e-3f));
    pb[1] = __logf(fmaxf(fabsf((cy - 0.5f * (Bb.y + Bb.w)) / bh), 1e-3f));
    pb[2] = __logf((Bb.z - Bb.x + 1.0f) / bw);
    pb[3] = __logf((Bb.w - Bb.y + 1.0f) / bh);

    unsigned long long acc[NG];
#pragma unroll
    for (int g = 0; g < NG; g++) acc[g] = 0ull;

    const ulonglong2* wq2 = (const ulonglong2*)wq;
#pragma unroll
    for (int p = 0; p < 4; p++) {
        float b0 = 100.0f * pa[p], b1 = 100.0f * pb[p];
#pragma unroll
        for (int j = 0; j < 8; j++) {
            float s0, cv0, s1, cv1;
            __sincosf(b0 * c_invdim[j], &s0, &cv0);
            __sincosf(b1 * c_invdim[j], &s1, &cv1);
            s0 = fmaxf(s0, 0.0f);  s1 = fmaxf(s1, 0.0f);
            cv0 = fmaxf(cv0, 0.0f); cv1 = fmaxf(cv1, 0.0f);
            unsigned long long ss, cc;
            asm("mov.b64 %0, {%1, %2};" : "=l"(ss) : "f"(s0), "f"(s1));
            asm("mov.b64 %0, {%1, %2};" : "=l"(cc) : "f"(cv0), "f"(cv1));
            int e = (p * 8 + j) * 16;
#pragma unroll
            for (int g = 0; g < NG; g++) {
                ulonglong2 w = wq2[e + g];
                asm("fma.rn.f32x2 %0, %1, %2, %0;" : "+l"(acc[g]) : "l"(ss), "l"(w.x));
                asm("fma.rn.f32x2 %0, %1, %2, %0;" : "+l"(acc[g]) : "l"(cc), "l"(w.y));
            }
        }
    }

    size_t o0 = (size_t)r * Ccols + c0;
    size_t sbase = (size_t)r * srow + (size_t)c0 * scol;
#pragma unroll
    for (int g = 0; g < NG; g++) {
        float a0, a1;
        asm("mov.b64 {%0, %1}, %2;" : "=f"(a0), "=f"(a1) : "l"(acc[g]));
        float v0 = __logf(fmaxf(a0 + bp[g], 1e-6f)) + scores[(size_t)g * MN + sbase];
        float v1 = __logf(fmaxf(a1 + bp[g], 1e-6f)) + scores[(size_t)g * MN + sbase + scol];
        float2 st; st.x = v0; st.y = v1;
        *(float2*)(L + (size_t)g * MN + o0) = st;
    }
}

// ---------------------------------------------------------------------------
// In-place row softmax. grid = nrows, block = 256, rowlen in {512, 1024}.
// ---------------------------------------------------------------------------
__global__ __launch_bounds__(256) void softmax_rows(float* __restrict__ buf, int rowlen)
{
    float* row = buf + (size_t)blockIdx.x * rowlen;
    int tid = threadIdx.x;
    int n = rowlen >> 8;
    float v[4];
    float m = -3.4e38f;
    #pragma unroll
    for (int i = 0; i < 4; i++)
        if (i < n) { v[i] = row[tid + (i << 8)]; m = fmaxf(m, v[i]); }

    __shared__ float sm[8];
    #pragma unroll
    for (int o = 16; o; o >>= 1) m = fmaxf(m, __shfl_xor_sync(0xffffffffu, m, o));
    if ((tid & 31) == 0) sm[tid >> 5] = m;
    __syncthreads();
    if (tid == 0) {
        float t = sm[0];
        #pragma unroll
        for (int i = 1; i < 8; i++) t = fmaxf(t, sm[i]);
        sm[0] = t;
    }
    __syncthreads();
    m = sm[0];

    float s = 0.0f;
    #pragma unroll
    for (int i = 0; i < 4; i++)
        if (i < n) { v[i] = __expf(v[i] - m); s += v[i]; }

    __syncthreads();
    #pragma unroll
    for (int o = 16; o; o >>= 1) s += __shfl_xor_sync(0xffffffffu, s, o);
    if ((tid & 31) == 0) sm[tid >> 5] = s;
    __syncthreads();
    if (tid == 0) {
        float t = 0.0f;
        #pragma unroll
        for (int i = 0; i < 8; i++) t += sm[i];
        sm[0] = t;
    }
    __syncthreads();
    float inv = 1.0f / sm[0];
    #pragma unroll
    for (int i = 0; i < 4; i++)
        if (i < n) row[tid + (i << 8)] = v[i] * inv;
}

// ---------------------------------------------------------------------------
extern "C" void kernel_launch(void* const* d_in, const int* in_sizes, int n_in,
                              void* d_out, int out_size)
{
    (void)in_sizes; (void)n_in; (void)out_size;
    const float* feat      = (const float*)d_in[0];
    const float* ctx_feat  = (const float*)d_in[1];
    const float* box       = (const float*)d_in[2];
    const float* ctx_box   = (const float*)d_in[3];
    const float* w_fc_gt   = (const float*)d_in[4];
    const float* b_fc_gt   = (const float*)d_in[5];
    const float* w_fc_ctx  = (const float*)d_in[6];
    const float* b_fc_ctx  = (const float*)d_in[7];
    const float* w_pos_gt  = (const float*)d_in[8];
    const float* b_pos_gt  = (const float*)d_in[9];
    const float* w_pos_ctx = (const float*)d_in[10];
    const float* b_pos_ctx = (const float*)d_in[11];
    const float* w_conv    = (const float*)d_in[12];
    const float* b_conv    = (const float*)d_in[13];

    float* out = (float*)d_out;
    float* out_gt  = out;
    float* out_ctx = out + (size_t)M_GT * FEAT;

    float *S, *L1, *L2;
    cudaGetSymbolAddress((void**)&S,  g_S);
    cudaGetSymbolAddress((void**)&L1, g_L1);
    cudaGetSymbolAddress((void**)&L2, g_L2);

    // 1) Q, K, Ut, Vt projections (tf32 mma.sync)
    proj_mma<<<dim3(8, 8, 4), 256>>>(feat, ctx_feat, w_fc_gt, b_fc_gt,
                                     w_fc_ctx, b_fc_ctx, w_conv);
    // 2) scores (G, M, N)
    scores_mma<<<dim3(8, 4, 16), 256>>>();
    // 3) fused position-embedding logits
    pos_logit2<<<dim3(2, M_GT), 256>>>((const float4*)box, (const float4*)ctx_box,
                                       w_pos_gt, b_pos_gt, S, N_CTX, 1, L1, N_CTX);
    pos_logit2<<<dim3(1, N_CTX), 256>>>((const float4*)ctx_box, (const float4*)box,
                                        w_pos_ctx, b_pos_ctx, S, 1, N_CTX, L2, M_GT);
    // 4) softmax rows
    softmax_rows<<<NG * M_GT,  256>>>(L1, N_CTX);
    softmax_rows<<<NG * N_CTX, 256>>>(L2, M_GT);
    // 5) attention output (tf32 mma.sync)
    attn_mma<<<dim3(1, 8, 32), 256>>>(b_conv, out_gt, out_ctx);
}

// round 6
// speedup vs baseline: 2.2350x; 1.1031x over previous
#include <cuda_runtime.h>
#include <cstdint>

#define M_GT  512
#define N_CTX 1024
#define FEAT  1024
#define NG    16
#define DK    64
#define MN    (M_GT * N_CTX)   // 524288

// ---------------- device scratch (static globals; no allocation) ------------
__device__ float g_Q [M_GT * FEAT];
__device__ float g_K [N_CTX * FEAT];
__device__ float g_Ut[FEAT * M_GT];    // Ut[o][m]
__device__ float g_Vt[FEAT * N_CTX];   // Vt[o][n]
__device__ float g_S [NG * MN];        // scores  (G, M, N)
__device__ float g_St[NG * MN];        // scores^T (G, N, M)
__device__ float g_L1[NG * MN];        // weights gt  (G, M, N)
__device__ float g_L2[NG * MN];        // weights ctx (G, N, M)

// 1000^(-j/8)
__constant__ float c_invdim[8] = {
    1.0f, 0.4216965034f, 0.1778279410f, 0.0749894209f,
    0.0316227766f, 0.0133352143f, 0.0056234133f, 0.0023713737f
};

// ======================= mma.sync tf32 helpers ==============================
__device__ __forceinline__ uint32_t f2tf(float x) {
    uint32_t r;
    asm("cvt.rna.tf32.f32 %0, %1;" : "=r"(r) : "f"(x));
    return r;
}

__device__ __forceinline__ void mma8(float* c, const uint32_t* a, const uint32_t* b) {
    asm volatile(
        "mma.sync.aligned.m16n8k8.row.col.f32.tf32.tf32.f32 "
        "{%0,%1,%2,%3}, {%4,%5,%6,%7}, {%8,%9}, {%0,%1,%2,%3};"
        : "+f"(c[0]), "+f"(c[1]), "+f"(c[2]), "+f"(c[3])
        : "r"(a[0]), "r"(a[1]), "r"(a[2]), "r"(a[3]), "r"(b[0]), "r"(b[1]));
}

#define LDP 36   // smem row pitch (floats)

template <int ROWS>
__device__ __forceinline__ void stage(const float* __restrict__ g, int ld,
                                      uint32_t* __restrict__ sm, int tid)
{
#pragma unroll
    for (int i = 0; i < ROWS / 32; i++) {
        int idx = tid + i * 256;
        int r = idx >> 3, c = (idx & 7) << 2;
        float4 v = *(const float4*)(g + (size_t)r * ld + c);
        uint4 t;
        t.x = f2tf(v.x); t.y = f2tf(v.y); t.z = f2tf(v.z); t.w = f2tf(v.w);
        *(uint4*)(sm + r * LDP + c) = t;
    }
}

// ---------------------------------------------------------------------------
// proj_mma: C = A @ W^T (+bias along N). 128x128 tiles, K=1024.
// ---------------------------------------------------------------------------
__global__ __launch_bounds__(256, 2) void proj_mma(
    const float* __restrict__ feat, const float* __restrict__ ctx_feat,
    const float* __restrict__ w_gt, const float* __restrict__ b_gt,
    const float* __restrict__ w_ctx, const float* __restrict__ b_ctx,
    const float* __restrict__ w_conv)
{
    const float* A; const float* W; const float* bias; float* C;
    int Mrows, Ncols;
    switch (blockIdx.z) {
    case 0:  A = feat;   W = w_gt;     bias = b_gt;  C = g_Q;  Mrows = M_GT;  Ncols = FEAT;  break;
    case 1:  A = ctx_feat; W = w_ctx;  bias = b_ctx; C = g_K;  Mrows = N_CTX; Ncols = FEAT;  break;
    case 2:  A = w_conv; W = feat;     bias = 0;     C = g_Ut; Mrows = FEAT;  Ncols = M_GT;  break;
    default: A = w_conv; W = ctx_feat; bias = 0;     C = g_Vt; Mrows = FEAT;  Ncols = N_CTX; break;
    }
    int bm = blockIdx.y * 128, bn = blockIdx.x * 128;
    if (bm >= Mrows || bn >= Ncols) return;

    __shared__ uint32_t As[128 * LDP];
    __shared__ uint32_t Bs[128 * LDP];

    int tid = threadIdx.x, wid = tid >> 5, lane = tid & 31;
    int g4 = lane >> 2, tig = lane & 3;
    int wm = (wid & 1) * 64, wn = (wid >> 1) * 32;

    float acc[4][4][4];
#pragma unroll
    for (int i = 0; i < 4; i++)
#pragma unroll
        for (int j = 0; j < 4; j++)
#pragma unroll
            for (int q = 0; q < 4; q++) acc[i][j][q] = 0.0f;

    const float* Ab = A + (size_t)bm * FEAT;
    const float* Wb = W + (size_t)bn * FEAT;

    for (int ch = 0; ch < FEAT / 32; ch++) {
        stage<128>(Ab + ch * 32, FEAT, As, tid);
        stage<128>(Wb + ch * 32, FEAT, Bs, tid);
        __syncthreads();
#pragma unroll
        for (int kk = 0; kk < 4; kk++) {
            int k0 = kk * 8 + tig;
            uint32_t bf[4][2];
#pragma unroll
            for (int j = 0; j < 4; j++) {
                int rn = (wn + j * 8 + g4) * LDP;
                bf[j][0] = Bs[rn + k0];
                bf[j][1] = Bs[rn + k0 + 4];
            }
#pragma unroll
            for (int i = 0; i < 4; i++) {
                int r0 = (wm + i * 16 + g4) * LDP;
                uint32_t af[4];
                af[0] = As[r0 + k0];
                af[1] = As[r0 + 8 * LDP + k0];
                af[2] = As[r0 + k0 + 4];
                af[3] = As[r0 + 8 * LDP + k0 + 4];
#pragma unroll
                for (int j = 0; j < 4; j++) mma8(acc[i][j], af, bf[j]);
            }
        }
        __syncthreads();
    }

#pragma unroll
    for (int i = 0; i < 4; i++) {
        int row = bm + wm + i * 16 + g4;
#pragma unroll
        for (int j = 0; j < 4; j++) {
            int col = bn + wn + j * 8 + 2 * tig;
            float b0 = bias ? bias[col] : 0.0f;
            float b1 = bias ? bias[col + 1] : 0.0f;
            float2 o0, o1;
            o0.x = acc[i][j][0] + b0; o0.y = acc[i][j][1] + b1;
            o1.x = acc[i][j][2] + b0; o1.y = acc[i][j][3] + b1;
            *(float2*)(C + (size_t)row * Ncols + col)       = o0;
            *(float2*)(C + (size_t)(row + 8) * Ncols + col) = o1;
        }
    }
}

// ---------------------------------------------------------------------------
// scores_mma: S[g,m,n] = 0.125 * sum_d Q.K ; also writes St[g,n,m].
// ---------------------------------------------------------------------------
__global__ __launch_bounds__(256, 2) void scores_mma()
{
    int g = blockIdx.z;
    int bm = blockIdx.y * 128, bn = blockIdx.x * 128;
    const float* A = g_Q + (size_t)bm * FEAT + g * DK;
    const float* B = g_K + (size_t)bn * FEAT + g * DK;
    float* C  = g_S  + (size_t)g * MN;
    float* Ct = g_St + (size_t)g * MN;

    __shared__ uint32_t As[128 * LDP];
    __shared__ uint32_t Bs[128 * LDP];

    int tid = threadIdx.x, wid = tid >> 5, lane = tid & 31;
    int g4 = lane >> 2, tig = lane & 3;
    int wm = (wid & 1) * 64, wn = (wid >> 1) * 32;

    float acc[4][4][4];
#pragma unroll
    for (int i = 0; i < 4; i++)
#pragma unroll
        for (int j = 0; j < 4; j++)
#pragma unroll
            for (int q = 0; q < 4; q++) acc[i][j][q] = 0.0f;

    for (int ch = 0; ch < 2; ch++) {
        stage<128>(A + ch * 32, FEAT, As, tid);
        stage<128>(B + ch * 32, FEAT, Bs, tid);
        __syncthreads();
#pragma unroll
        for (int kk = 0; kk < 4; kk++) {
            int k0 = kk * 8 + tig;
            uint32_t bf[4][2];
#pragma unroll
            for (int j = 0; j < 4; j++) {
                int rn = (wn + j * 8 + g4) * LDP;
                bf[j][0] = Bs[rn + k0];
                bf[j][1] = Bs[rn + k0 + 4];
            }
#pragma unroll
            for (int i = 0; i < 4; i++) {
                int r0 = (wm + i * 16 + g4) * LDP;
                uint32_t af[4];
                af[0] = As[r0 + k0];
                af[1] = As[r0 + 8 * LDP + k0];
                af[2] = As[r0 + k0 + 4];
                af[3] = As[r0 + 8 * LDP + k0 + 4];
#pragma unroll
                for (int j = 0; j < 4; j++) mma8(acc[i][j], af, bf[j]);
            }
        }
        __syncthreads();
    }

#pragma unroll
    for (int i = 0; i < 4; i++) {
        int row = bm + wm + i * 16 + g4;
#pragma unroll
        for (int j = 0; j < 4; j++) {
            int col = bn + wn + j * 8 + 2 * tig;
            float v00 = acc[i][j][0] * 0.125f, v01 = acc[i][j][1] * 0.125f;
            float v10 = acc[i][j][2] * 0.125f, v11 = acc[i][j][3] * 0.125f;
            float2 o0, o1;
            o0.x = v00; o0.y = v01; o1.x = v10; o1.y = v11;
            *(float2*)(C + (size_t)row * N_CTX + col)       = o0;
            *(float2*)(C + (size_t)(row + 8) * N_CTX + col) = o1;
            // transposed: St[n][m]
            Ct[(size_t)col * M_GT + row]           = v00;
            Ct[(size_t)(col + 1) * M_GT + row]     = v01;
            Ct[(size_t)col * M_GT + row + 8]       = v10;
            Ct[(size_t)(col + 1) * M_GT + row + 8] = v11;
        }
    }
}

// ---------------------------------------------------------------------------
// attn_mma: z 0..15 gt, z 16..31 ctx. 128x64 tiles, warp tile 64x16.
// ---------------------------------------------------------------------------
__global__ __launch_bounds__(256, 2) void attn_mma(
    const float* __restrict__ b_conv, float* __restrict__ out_gt,
    float* __restrict__ out_ctx)
{
    int z = blockIdx.z;
    int g = z & 15;
    bool gt = z < 16;
    const float* A = gt ? g_L1 + (size_t)g * MN : g_L2 + (size_t)g * MN;
    const float* B = gt ? g_Vt + (size_t)(g * DK) * N_CTX
                        : g_Ut + (size_t)(g * DK) * M_GT;
    float* C  = gt ? out_gt : out_ctx;
    int Mrows = gt ? M_GT : N_CTX;
    int Ktot  = gt ? N_CTX : M_GT;
    int bm = blockIdx.y * 128;
    if (bm >= Mrows) return;

    __shared__ uint32_t As[128 * LDP];
    __shared__ uint32_t Bs[64 * LDP];

    int tid = threadIdx.x, wid = tid >> 5, lane = tid & 31;
    int g4 = lane >> 2, tig = lane & 3;
    int wm = (wid & 1) * 64, wn = (wid >> 1) * 16;

    float acc[4][2][4];
#pragma unroll
    for (int i = 0; i < 4; i++)
#pragma unroll
        for (int j = 0; j < 2; j++)
#pragma unroll
            for (int q = 0; q < 4; q++) acc[i][j][q] = 0.0f;

    const float* Ab = A + (size_t)bm * Ktot;

    for (int ch = 0; ch < Ktot / 32; ch++) {
        stage<128>(Ab + ch * 32, Ktot, As, tid);
        stage<64> (B  + ch * 32, Ktot, Bs, tid);
        __syncthreads();
#pragma unroll
        for (int kk = 0; kk < 4; kk++) {
            int k0 = kk * 8 + tig;
            uint32_t bf[2][2];
#pragma unroll
            for (int j = 0; j < 2; j++) {
                int rn = (wn + j * 8 + g4) * LDP;
                bf[j][0] = Bs[rn + k0];
                bf[j][1] = Bs[rn + k0 + 4];
            }
#pragma unroll
            for (int i = 0; i < 4; i++) {
                int r0 = (wm + i * 16 + g4) * LDP;
                uint32_t af[4];
                af[0] = As[r0 + k0];
                af[1] = As[r0 + 8 * LDP + k0];
                af[2] = As[r0 + k0 + 4];
                af[3] = As[r0 + 8 * LDP + k0 + 4];
#pragma unroll
                for (int j = 0; j < 2; j++) mma8(acc[i][j], af, bf[j]);
            }
        }
        __syncthreads();
    }

#pragma unroll
    for (int i = 0; i < 4; i++) {
        int row = bm + wm + i * 16 + g4;
#pragma unroll
        for (int j = 0; j < 2; j++) {
            int col = g * DK + wn + j * 8 + 2 * tig;
            float b0 = b_conv[col], b1 = b_conv[col + 1];
            float2 o0, o1;
            o0.x = acc[i][j][0] + b0; o0.y = acc[i][j][1] + b1;
            o1.x = acc[i][j][2] + b0; o1.y = acc[i][j][3] + b1;
            *(float2*)(C + (size_t)row * FEAT + col)       = o0;
            *(float2*)(C + (size_t)(row + 8) * FEAT + col) = o1;
        }
    }
}

// ---------------------------------------------------------------------------
// pos_soft<NCOLS>: fused pos-embedding + logit + row softmax.
// One block per row r; NCOLS/4 threads, 4 columns per thread.
// Sb layout: [g][r][c] with c contiguous (NCOLS). Output same layout.
// ---------------------------------------------------------------------------
template <int NCOLS>
__global__ __launch_bounds__(NCOLS / 4) void pos_soft(
    const float4* __restrict__ boxA, const float4* __restrict__ boxB,
    const float* __restrict__ w_pos, const float* __restrict__ b_pos,
    const float* __restrict__ Sb, float* __restrict__ L)
{
    constexpr int NT = NCOLS / 4;
    constexpr int NW = NT / 32;
    __shared__ __align__(16) float wq[512 * 4];   // [(p*8+j)*16+g] = {ws,ws,wc,wc}
    __shared__ float bp[NG];
    __shared__ float rbuf[NG * (NW + 1)];

    int tid = threadIdx.x, wid = tid >> 5, lane = tid & 31;
    for (int i = tid; i < 512; i += NT) {
        int pj = i >> 4, g = i & 15;
        int p = pj >> 3, j = pj & 7;
        float ws = w_pos[g * 64 + p * 16 + j];
        float wc = w_pos[g * 64 + p * 16 + 8 + j];
        wq[i * 4 + 0] = ws; wq[i * 4 + 1] = ws;
        wq[i * 4 + 2] = wc; wq[i * 4 + 3] = wc;
    }
    if (tid < NG) bp[tid] = b_pos[tid];
    __syncthreads();

    int r = blockIdx.x;
    int c0 = tid * 4;

    float4 A = boxA[r];
    float bw = A.z - A.x + 1.0f, bh = A.w - A.y + 1.0f;
    float cx = 0.5f * (A.x + A.z), cy = 0.5f * (A.y + A.w);

    float pp[4][4];
#pragma unroll
    for (int q = 0; q < 4; q++) {
        float4 Bx = boxB[c0 + q];
        pp[q][0] = __logf(fmaxf(fabsf((cx - 0.5f * (Bx.x + Bx.z)) / bw), 1e-3f));
        pp[q][1] = __logf(fmaxf(fabsf((cy - 0.5f * (Bx.y + Bx.w)) / bh), 1e-3f));
        pp[q][2] = __logf((Bx.z - Bx.x + 1.0f) / bw);
        pp[q][3] = __logf((Bx.w - Bx.y + 1.0f) / bh);
    }

    unsigned long long acc[NG][2];
#pragma unroll
    for (int g = 0; g < NG; g++) { acc[g][0] = 0ull; acc[g][1] = 0ull; }

    const ulonglong2* wq2 = (const ulonglong2*)wq;
#pragma unroll
    for (int p = 0; p < 4; p++) {
        float b0 = 100.0f * pp[0][p], b1 = 100.0f * pp[1][p];
        float b2 = 100.0f * pp[2][p], b3 = 100.0f * pp[3][p];
#pragma unroll
        for (int j = 0; j < 8; j++) {
            float iv = c_invdim[j];
            float s0, v0, s1, v1, s2, v2, s3, v3;
            __sincosf(b0 * iv, &s0, &v0);
            __sincosf(b1 * iv, &s1, &v1);
            __sincosf(b2 * iv, &s2, &v2);
            __sincosf(b3 * iv, &s3, &v3);
            s0 = fmaxf(s0, 0.0f); s1 = fmaxf(s1, 0.0f);
            s2 = fmaxf(s2, 0.0f); s3 = fmaxf(s3, 0.0f);
            v0 = fmaxf(v0, 0.0f); v1 = fmaxf(v1, 0.0f);
            v2 = fmaxf(v2, 0.0f); v3 = fmaxf(v3, 0.0f);
            unsigned long long ss01, ss23, cc01, cc23;
            asm("mov.b64 %0, {%1, %2};" : "=l"(ss01) : "f"(s0), "f"(s1));
            asm("mov.b64 %0, {%1, %2};" : "=l"(ss23) : "f"(s2), "f"(s3));
            asm("mov.b64 %0, {%1, %2};" : "=l"(cc01) : "f"(v0), "f"(v1));
            asm("mov.b64 %0, {%1, %2};" : "=l"(cc23) : "f"(v2), "f"(v3));
            int e = (p * 8 + j) * 16;
#pragma unroll
            for (int g = 0; g < NG; g++) {
                ulonglong2 w = wq2[e + g];
                asm("fma.rn.f32x2 %0, %1, %2, %0;" : "+l"(acc[g][0]) : "l"(ss01), "l"(w.x));
                asm("fma.rn.f32x2 %0, %1, %2, %0;" : "+l"(acc[g][1]) : "l"(ss23), "l"(w.x));
                asm("fma.rn.f32x2 %0, %1, %2, %0;" : "+l"(acc[g][0]) : "l"(cc01), "l"(w.y));
                asm("fma.rn.f32x2 %0, %1, %2, %0;" : "+l"(acc[g][1]) : "l"(cc23), "l"(w.y));
            }
        }
    }

    // logits
    float l[NG][4];
    float mx[NG];
#pragma unroll
    for (int g = 0; g < NG; g++) {
        float a0, a1, a2, a3;
        asm("mov.b64 {%0, %1}, %2;" : "=f"(a0), "=f"(a1) : "l"(acc[g][0]));
        asm("mov.b64 {%0, %1}, %2;" : "=f"(a2), "=f"(a3) : "l"(acc[g][1]));
        float4 sc = *(const float4*)(Sb + (size_t)g * MN + (size_t)r * NCOLS + c0);
        float bg = bp[g];
        l[g][0] = __logf(fmaxf(a0 + bg, 1e-6f)) + sc.x;
        l[g][1] = __logf(fmaxf(a1 + bg, 1e-6f)) + sc.y;
        l[g][2] = __logf(fmaxf(a2 + bg, 1e-6f)) + sc.z;
        l[g][3] = __logf(fmaxf(a3 + bg, 1e-6f)) + sc.w;
        float m01 = fmaxf(l[g][0], l[g][1]);
        float m23 = fmaxf(l[g][2], l[g][3]);
        mx[g] = fmaxf(m01, m23);
    }

    // block max per g
#pragma unroll
    for (int g = 0; g < NG; g++) {
#pragma unroll
        for (int o = 16; o; o >>= 1)
            mx[g] = fmaxf(mx[g], __shfl_xor_sync(0xffffffffu, mx[g], o));
    }
    if (lane == 0) {
#pragma unroll
        for (int g = 0; g < NG; g++) rbuf[g * (NW + 1) + wid] = mx[g];
    }
    __syncthreads();
    if (tid < NG) {
        float t = rbuf[tid * (NW + 1)];
#pragma unroll
        for (int w = 1; w < NW; w++) t = fmaxf(t, rbuf[tid * (NW + 1) + w]);
        rbuf[tid * (NW + 1) + NW] = t;
    }
    __syncthreads();

    float sum[NG];
#pragma unroll
    for (int g = 0; g < NG; g++) {
        float m = rbuf[g * (NW + 1) + NW];
        l[g][0] = __expf(l[g][0] - m);
        l[g][1] = __expf(l[g][1] - m);
        l[g][2] = __expf(l[g][2] - m);
        l[g][3] = __expf(l[g][3] - m);
        sum[g] = (l[g][0] + l[g][1]) + (l[g][2] + l[g][3]);
    }
    __syncthreads();   // rbuf reuse
#pragma unroll
    for (int g = 0; g < NG; g++) {
#pragma unroll
        for (int o = 16; o; o >>= 1)
            sum[g] += __shfl_xor_sync(0xffffffffu, sum[g], o);
    }
    if (lane == 0) {
#pragma unroll
        for (int g = 0; g < NG; g++) rbuf[g * (NW + 1) + wid] = sum[g];
    }
    __syncthreads();
    if (tid < NG) {
        float t = 0.0f;
#pragma unroll
        for (int w = 0; w < NW; w++) t += rbuf[tid * (NW + 1) + w];
        rbuf[tid * (NW + 1) + NW] = t;
    }
    __syncthreads();

#pragma unroll
    for (int g = 0; g < NG; g++) {
        float inv = __frcp_rn(rbuf[g * (NW + 1) + NW]);
        float4 o;
        o.x = l[g][0] * inv; o.y = l[g][1] * inv;
        o.z = l[g][2] * inv; o.w = l[g][3] * inv;
        *(float4*)(L + (size_t)g * MN + (size_t)r * NCOLS + c0) = o;
    }
}

// ---------------------------------------------------------------------------
extern "C" void kernel_launch(void* const* d_in, const int* in_sizes, int n_in,
                              void* d_out, int out_size)
{
    (void)in_sizes; (void)n_in; (void)out_size;
    const float* feat      = (const float*)d_in[0];
    const float* ctx_feat  = (const float*)d_in[1];
    const float* box       = (const float*)d_in[2];
    const float* ctx_box   = (const float*)d_in[3];
    const float* w_fc_gt   = (const float*)d_in[4];
    const float* b_fc_gt   = (const float*)d_in[5];
    const float* w_fc_ctx  = (const float*)d_in[6];
    const float* b_fc_ctx  = (const float*)d_in[7];
    const float* w_pos_gt  = (const float*)d_in[8];
    const float* b_pos_gt  = (const float*)d_in[9];
    const float* w_pos_ctx = (const float*)d_in[10];
    const float* b_pos_ctx = (const float*)d_in[11];
    const float* w_conv    = (const float*)d_in[12];
    const float* b_conv    = (const float*)d_in[13];

    float* out = (float*)d_out;
    float* out_gt  = out;
    float* out_ctx = out + (size_t)M_GT * FEAT;

    float *S, *St, *L1, *L2;
    cudaGetSymbolAddress((void**)&S,  g_S);
    cudaGetSymbolAddress((void**)&St, g_St);
    cudaGetSymbolAddress((void**)&L1, g_L1);
    cudaGetSymbolAddress((void**)&L2, g_L2);

    // 1) Q, K, Ut, Vt projections (tf32 mma.sync)
    proj_mma<<<dim3(8, 8, 4), 256>>>(feat, ctx_feat, w_fc_gt, b_fc_gt,
                                     w_fc_ctx, b_fc_ctx, w_conv);
    // 2) scores S + St
    scores_mma<<<dim3(8, 4, 16), 256>>>();
    // 3) fused pos-embedding + logits + softmax
    pos_soft<N_CTX><<<M_GT, N_CTX / 4>>>((const float4*)box, (const float4*)ctx_box,
                                         w_pos_gt, b_pos_gt, S, L1);
    pos_soft<M_GT><<<N_CTX, M_GT / 4>>>((const float4*)ctx_box, (const float4*)box,
                                        w_pos_ctx, b_pos_ctx, St, L2);
    // 4) attention output (tf32 mma.sync)
    attn_mma<<<dim3(1, 8, 32), 256>>>(b_conv, out_gt, out_ctx);
}

// round 7
// speedup vs baseline: 2.2365x; 1.0007x over previous
#include <cuda_runtime.h>
#include <cstdint>

#define M_GT  512
#define N_CTX 1024
#define FEAT  1024
#define NG    16
#define DK    64
#define MN    (M_GT * N_CTX)   // 524288

// ---------------- device scratch (static globals; no allocation) ------------
__device__ float g_Q [M_GT * FEAT];
__device__ float g_K [N_CTX * FEAT];
__device__ float g_Ut[FEAT * M_GT];    // Ut[o][m]
__device__ float g_Vt[FEAT * N_CTX];   // Vt[o][n]
__device__ float g_S [NG * MN];        // scores  (G, M, N)
__device__ float g_St[NG * MN];        // scores^T (G, N, M)
__device__ float g_L1[NG * MN];        // weights gt  (G, M, N)
__device__ float g_L2[NG * MN];        // weights ctx (G, N, M)

// 1000^(-j/8)
__constant__ float c_invdim[8] = {
    1.0f, 0.4216965034f, 0.1778279410f, 0.0749894209f,
    0.0316227766f, 0.0133352143f, 0.0056234133f, 0.0023713737f
};

// ======================= helpers ==========================
__device__ __forceinline__ uint32_t f2tf(float x) {
    uint32_t r;
    asm("cvt.rna.tf32.f32 %0, %1;" : "=r"(r) : "f"(x));
    return r;
}

__device__ __forceinline__ void mma8(float* c, const uint32_t* a, const uint32_t* b) {
    asm volatile(
        "mma.sync.aligned.m16n8k8.row.col.f32.tf32.tf32.f32 "
        "{%0,%1,%2,%3}, {%4,%5,%6,%7}, {%8,%9}, {%0,%1,%2,%3};"
        : "+f"(c[0]), "+f"(c[1]), "+f"(c[2]), "+f"(c[3])
        : "r"(a[0]), "r"(a[1]), "r"(a[2]), "r"(a[3]), "r"(b[0]), "r"(b[1]));
}

__device__ __forceinline__ void cp16(uint32_t s, const void* g) {
    asm volatile("cp.async.cg.shared.global [%0], [%1], 16;" :: "r"(s), "l"(g));
}
#define CP_COMMIT() asm volatile("cp.async.commit_group;" ::: "memory")
#define CP_WAIT1()  asm volatile("cp.async.wait_group 1;" ::: "memory")
#define CP_WAIT0()  asm volatile("cp.async.wait_group 0;" ::: "memory")

#define LDP 36   // smem row pitch (floats)

// cp.async issue of a ROWSx32 fp32 chunk into smem [ROWS][LDP] (raw fp32)
template <int ROWS>
__device__ __forceinline__ void issue_chunk(const float* __restrict__ g, int ld,
                                            uint32_t smbase, int tid)
{
#pragma unroll
    for (int i = 0; i < ROWS / 32; i++) {
        int idx = tid + i * 256;
        int r = idx >> 3, c = (idx & 7) << 2;
        cp16(smbase + (uint32_t)(r * LDP + c) * 4u, g + (size_t)r * ld + c);
    }
}

// sync staging with rna cvt (used by scores_mma)
template <int ROWS>
__device__ __forceinline__ void stage(const float* __restrict__ g, int ld,
                                      uint32_t* __restrict__ sm, int tid)
{
#pragma unroll
    for (int i = 0; i < ROWS / 32; i++) {
        int idx = tid + i * 256;
        int r = idx >> 3, c = (idx & 7) << 2;
        float4 v = *(const float4*)(g + (size_t)r * ld + c);
        uint4 t;
        t.x = f2tf(v.x); t.y = f2tf(v.y); t.z = f2tf(v.z); t.w = f2tf(v.w);
        *(uint4*)(sm + r * LDP + c) = t;
    }
}

// ---------------------------------------------------------------------------
// proj_mma: C = A @ W^T (+bias along N). 128x128 tiles, K=1024.
// cp.async double-buffered; cvt.rna at fragment load.
// ---------------------------------------------------------------------------
#define PROJ_BUF (128 * LDP * 2)   // floats per buffer (A tile + B tile)

__global__ __launch_bounds__(256, 2) void proj_mma(
    const float* __restrict__ feat, const float* __restrict__ ctx_feat,
    const float* __restrict__ w_gt, const float* __restrict__ b_gt,
    const float* __restrict__ w_ctx, const float* __restrict__ b_ctx,
    const float* __restrict__ w_conv)
{
    const float* A; const float* W; const float* bias; float* C;
    int Mrows, Ncols;
    switch (blockIdx.z) {
    case 0:  A = feat;   W = w_gt;     bias = b_gt;  C = g_Q;  Mrows = M_GT;  Ncols = FEAT;  break;
    case 1:  A = ctx_feat; W = w_ctx;  bias = b_ctx; C = g_K;  Mrows = N_CTX; Ncols = FEAT;  break;
    case 2:  A = w_conv; W = feat;     bias = 0;     C = g_Ut; Mrows = FEAT;  Ncols = M_GT;  break;
    default: A = w_conv; W = ctx_feat; bias = 0;     C = g_Vt; Mrows = FEAT;  Ncols = N_CTX; break;
    }
    int bm = blockIdx.y * 128, bn = blockIdx.x * 128;
    if (bm >= Mrows || bn >= Ncols) return;

    extern __shared__ float dsm[];
    uint32_t smb = (uint32_t)__cvta_generic_to_shared(dsm);

    int tid = threadIdx.x, wid = tid >> 5, lane = tid & 31;
    int g4 = lane >> 2, tig = lane & 3;
    int wm = (wid & 1) * 64, wn = (wid >> 1) * 32;

    float acc[4][4][4];
#pragma unroll
    for (int i = 0; i < 4; i++)
#pragma unroll
        for (int j = 0; j < 4; j++)
#pragma unroll
            for (int q = 0; q < 4; q++) acc[i][j][q] = 0.0f;

    const float* Ab = A + (size_t)bm * FEAT;
    const float* Wb = W + (size_t)bn * FEAT;

    // issue chunk 0 into buffer 0
    issue_chunk<128>(Ab, FEAT, smb, tid);
    issue_chunk<128>(Wb, FEAT, smb + 128 * LDP * 4u, tid);
    CP_COMMIT();

    const int NCH = FEAT / 32;
    for (int ch = 0; ch < NCH; ch++) {
        int buf = ch & 1;
        if (ch + 1 < NCH) {
            uint32_t nb = smb + (uint32_t)((ch + 1) & 1) * PROJ_BUF * 4u;
            issue_chunk<128>(Ab + (ch + 1) * 32, FEAT, nb, tid);
            issue_chunk<128>(Wb + (ch + 1) * 32, FEAT, nb + 128 * LDP * 4u, tid);
            CP_COMMIT();
            CP_WAIT1();
        } else {
            CP_WAIT0();
        }
        __syncthreads();
        const float* As = dsm + buf * PROJ_BUF;
        const float* Bs = As + 128 * LDP;
#pragma unroll
        for (int kk = 0; kk < 4; kk++) {
            int k0 = kk * 8 + tig;
            uint32_t bf[4][2];
#pragma unroll
            for (int j = 0; j < 4; j++) {
                int rn = (wn + j * 8 + g4) * LDP;
                bf[j][0] = f2tf(Bs[rn + k0]);
                bf[j][1] = f2tf(Bs[rn + k0 + 4]);
            }
#pragma unroll
            for (int i = 0; i < 4; i++) {
                int r0 = (wm + i * 16 + g4) * LDP;
                uint32_t af[4];
                af[0] = f2tf(As[r0 + k0]);
                af[1] = f2tf(As[r0 + 8 * LDP + k0]);
                af[2] = f2tf(As[r0 + k0 + 4]);
                af[3] = f2tf(As[r0 + 8 * LDP + k0 + 4]);
#pragma unroll
                for (int j = 0; j < 4; j++) mma8(acc[i][j], af, bf[j]);
            }
        }
        __syncthreads();
    }

#pragma unroll
    for (int i = 0; i < 4; i++) {
        int row = bm + wm + i * 16 + g4;
#pragma unroll
        for (int j = 0; j < 4; j++) {
            int col = bn + wn + j * 8 + 2 * tig;
            float b0 = bias ? bias[col] : 0.0f;
            float b1 = bias ? bias[col + 1] : 0.0f;
            float2 o0, o1;
            o0.x = acc[i][j][0] + b0; o0.y = acc[i][j][1] + b1;
            o1.x = acc[i][j][2] + b0; o1.y = acc[i][j][3] + b1;
            *(float2*)(C + (size_t)row * Ncols + col)       = o0;
            *(float2*)(C + (size_t)(row + 8) * Ncols + col) = o1;
        }
    }
}

// ---------------------------------------------------------------------------
// scores_mma: S[g,m,n] = 0.125 * Q.K ; also writes St[g,n,m]. K=64, 2 chunks.
// ---------------------------------------------------------------------------
__global__ __launch_bounds__(256, 2) void scores_mma()
{
    int g = blockIdx.z;
    int bm = blockIdx.y * 128, bn = blockIdx.x * 128;
    const float* A = g_Q + (size_t)bm * FEAT + g * DK;
    const float* B = g_K + (size_t)bn * FEAT + g * DK;
    float* C  = g_S  + (size_t)g * MN;
    float* Ct = g_St + (size_t)g * MN;

    __shared__ uint32_t As[128 * LDP];
    __shared__ uint32_t Bs[128 * LDP];

    int tid = threadIdx.x, wid = tid >> 5, lane = tid & 31;
    int g4 = lane >> 2, tig = lane & 3;
    int wm = (wid & 1) * 64, wn = (wid >> 1) * 32;

    float acc[4][4][4];
#pragma unroll
    for (int i = 0; i < 4; i++)
#pragma unroll
        for (int j = 0; j < 4; j++)
#pragma unroll
            for (int q = 0; q < 4; q++) acc[i][j][q] = 0.0f;

    for (int ch = 0; ch < 2; ch++) {
        stage<128>(A + ch * 32, FEAT, As, tid);
        stage<128>(B + ch * 32, FEAT, Bs, tid);
        __syncthreads();
#pragma unroll
        for (int kk = 0; kk < 4; kk++) {
            int k0 = kk * 8 + tig;
            uint32_t bf[4][2];
#pragma unroll
            for (int j = 0; j < 4; j++) {
                int rn = (wn + j * 8 + g4) * LDP;
                bf[j][0] = Bs[rn + k0];
                bf[j][1] = Bs[rn + k0 + 4];
            }
#pragma unroll
            for (int i = 0; i < 4; i++) {
                int r0 = (wm + i * 16 + g4) * LDP;
                uint32_t af[4];
                af[0] = As[r0 + k0];
                af[1] = As[r0 + 8 * LDP + k0];
                af[2] = As[r0 + k0 + 4];
                af[3] = As[r0 + 8 * LDP + k0 + 4];
#pragma unroll
                for (int j = 0; j < 4; j++) mma8(acc[i][j], af, bf[j]);
            }
        }
        __syncthreads();
    }

#pragma unroll
    for (int i = 0; i < 4; i++) {
        int row = bm + wm + i * 16 + g4;
#pragma unroll
        for (int j = 0; j < 4; j++) {
            int col = bn + wn + j * 8 + 2 * tig;
            float v00 = acc[i][j][0] * 0.125f, v01 = acc[i][j][1] * 0.125f;
            float v10 = acc[i][j][2] * 0.125f, v11 = acc[i][j][3] * 0.125f;
            float2 o0, o1;
            o0.x = v00; o0.y = v01; o1.x = v10; o1.y = v11;
            *(float2*)(C + (size_t)row * N_CTX + col)       = o0;
            *(float2*)(C + (size_t)(row + 8) * N_CTX + col) = o1;
            Ct[(size_t)col * M_GT + row]           = v00;
            Ct[(size_t)(col + 1) * M_GT + row]     = v01;
            Ct[(size_t)col * M_GT + row + 8]       = v10;
            Ct[(size_t)(col + 1) * M_GT + row + 8] = v11;
        }
    }
}

// ---------------------------------------------------------------------------
// attn_mma: z 0..15 gt, z 16..31 ctx. 128x64 tiles, warp tile 64x16.
// cp.async double-buffered.
// ---------------------------------------------------------------------------
#define ATTN_BUF (128 * LDP + 64 * LDP)   // floats per buffer

__global__ __launch_bounds__(256, 2) void attn_mma(
    const float* __restrict__ b_conv, float* __restrict__ out_gt,
    float* __restrict__ out_ctx)
{
    int z = blockIdx.z;
    int g = z & 15;
    bool gt = z < 16;
    const float* A = gt ? g_L1 + (size_t)g * MN : g_L2 + (size_t)g * MN;
    const float* B = gt ? g_Vt + (size_t)(g * DK) * N_CTX
                        : g_Ut + (size_t)(g * DK) * M_GT;
    float* C  = gt ? out_gt : out_ctx;
    int Mrows = gt ? M_GT : N_CTX;
    int Ktot  = gt ? N_CTX : M_GT;
    int bm = blockIdx.y * 128;
    if (bm >= Mrows) return;

    extern __shared__ float dsm[];
    uint32_t smb = (uint32_t)__cvta_generic_to_shared(dsm);

    int tid = threadIdx.x, wid = tid >> 5, lane = tid & 31;
    int g4 = lane >> 2, tig = lane & 3;
    int wm = (wid & 1) * 64, wn = (wid >> 1) * 16;

    float acc[4][2][4];
#pragma unroll
    for (int i = 0; i < 4; i++)
#pragma unroll
        for (int j = 0; j < 2; j++)
#pragma unroll
            for (int q = 0; q < 4; q++) acc[i][j][q] = 0.0f;

    const float* Ab = A + (size_t)bm * Ktot;

    issue_chunk<128>(Ab, Ktot, smb, tid);
    issue_chunk<64>(B, Ktot, smb + 128 * LDP * 4u, tid);
    CP_COMMIT();

    int NCH = Ktot / 32;
    for (int ch = 0; ch < NCH; ch++) {
        int buf = ch & 1;
        if (ch + 1 < NCH) {
            uint32_t nb = smb + (uint32_t)((ch + 1) & 1) * ATTN_BUF * 4u;
            issue_chunk<128>(Ab + (ch + 1) * 32, Ktot, nb, tid);
            issue_chunk<64>(B + (ch + 1) * 32, Ktot, nb + 128 * LDP * 4u, tid);
            CP_COMMIT();
            CP_WAIT1();
        } else {
            CP_WAIT0();
        }
        __syncthreads();
        const float* As = dsm + buf * ATTN_BUF;
        const float* Bs = As + 128 * LDP;
#pragma unroll
        for (int kk = 0; kk < 4; kk++) {
            int k0 = kk * 8 + tig;
            uint32_t bf[2][2];
#pragma unroll
            for (int j = 0; j < 2; j++) {
                int rn = (wn + j * 8 + g4) * LDP;
                bf[j][0] = f2tf(Bs[rn + k0]);
                bf[j][1] = f2tf(Bs[rn + k0 + 4]);
            }
#pragma unroll
            for (int i = 0; i < 4; i++) {
                int r0 = (wm + i * 16 + g4) * LDP;
                uint32_t af[4];
                af[0] = f2tf(As[r0 + k0]);
                af[1] = f2tf(As[r0 + 8 * LDP + k0]);
                af[2] = f2tf(As[r0 + k0 + 4]);
                af[3] = f2tf(As[r0 + 8 * LDP + k0 + 4]);
#pragma unroll
                for (int j = 0; j < 2; j++) mma8(acc[i][j], af, bf[j]);
            }
        }
        __syncthreads();
    }

#pragma unroll
    for (int i = 0; i < 4; i++) {
        int row = bm + wm + i * 16 + g4;
#pragma unroll
        for (int j = 0; j < 2; j++) {
            int col = g * DK + wn + j * 8 + 2 * tig;
            float b0 = b_conv[col], b1 = b_conv[col + 1];
            float2 o0, o1;
            o0.x = acc[i][j][0] + b0; o0.y = acc[i][j][1] + b1;
            o1.x = acc[i][j][2] + b0; o1.y = acc[i][j][3] + b1;
            *(float2*)(C + (size_t)row * FEAT + col)       = o0;
            *(float2*)(C + (size_t)(row + 8) * FEAT + col) = o1;
        }
    }
}

// ---------------------------------------------------------------------------
// pos_soft<NCOLS>: fused pos-embedding + logit + row softmax.
// One block per row; NCOLS/4 threads, 4 columns/thread.
// Logits live in DYNAMIC smem (not regs) to double occupancy.
// ---------------------------------------------------------------------------
template <int NCOLS>
__global__ __launch_bounds__(NCOLS / 4) void pos_soft(
    const float4* __restrict__ boxA, const float4* __restrict__ boxB,
    const float* __restrict__ w_pos, const float* __restrict__ b_pos,
    const float* __restrict__ Sb, float* __restrict__ L)
{
    constexpr int NT = NCOLS / 4;
    constexpr int NW = NT / 32;
    extern __shared__ float sl[];                 // [NG][NCOLS] logits
    __shared__ __align__(16) float wq[512 * 4];   // [(p*8+j)*16+g] = {ws,ws,wc,wc}
    __shared__ float bp[NG];
    __shared__ float rbuf[NG * (NW + 1)];

    int tid = threadIdx.x, wid = tid >> 5, lane = tid & 31;
    for (int i = tid; i < 512; i += NT) {
        int pj = i >> 4, g = i & 15;
        int p = pj >> 3, j = pj & 7;
        float ws = w_pos[g * 64 + p * 16 + j];
        float wc = w_pos[g * 64 + p * 16 + 8 + j];
        wq[i * 4 + 0] = ws; wq[i * 4 + 1] = ws;
        wq[i * 4 + 2] = wc; wq[i * 4 + 3] = wc;
    }
    if (tid < NG) bp[tid] = b_pos[tid];
    __syncthreads();

    int r = blockIdx.x;
    int c0 = tid * 4;

    float4 A = boxA[r];
    float bw = A.z - A.x + 1.0f, bh = A.w - A.y + 1.0f;
    float cx = 0.5f * (A.x + A.z), cy = 0.5f * (A.y + A.w);

    float pp[4][4];
#pragma unroll
    for (int q = 0; q < 4; q++) {
        float4 Bx = boxB[c0 + q];
        pp[q][0] = __logf(fmaxf(fabsf((cx - 0.5f * (Bx.x + Bx.z)) / bw), 1e-3f));
        pp[q][1] = __logf(fmaxf(fabsf((cy - 0.5f * (Bx.y + Bx.w)) / bh), 1e-3f));
        pp[q][2] = __logf((Bx.z - Bx.x + 1.0f) / bw);
        pp[q][3] = __logf((Bx.w - Bx.y + 1.0f) / bh);
    }

    unsigned long long acc[NG][2];
#pragma unroll
    for (int g = 0; g < NG; g++) { acc[g][0] = 0ull; acc[g][1] = 0ull; }

    const ulonglong2* wq2 = (const ulonglong2*)wq;
#pragma unroll
    for (int p = 0; p < 4; p++) {
        float b0 = 100.0f * pp[0][p], b1 = 100.0f * pp[1][p];
        float b2 = 100.0f * pp[2][p], b3 = 100.0f * pp[3][p];
#pragma unroll
        for (int j = 0; j < 8; j++) {
            float iv = c_invdim[j];
            float s0, v0, s1, v1, s2, v2, s3, v3;
            __sincosf(b0 * iv, &s0, &v0);
            __sincosf(b1 * iv, &s1, &v1);
            __sincosf(b2 * iv, &s2, &v2);
            __sincosf(b3 * iv, &s3, &v3);
            s0 = fmaxf(s0, 0.0f); s1 = fmaxf(s1, 0.0f);
            s2 = fmaxf(s2, 0.0f); s3 = fmaxf(s3, 0.0f);
            v0 = fmaxf(v0, 0.0f); v1 = fmaxf(v1, 0.0f);
            v2 = fmaxf(v2, 0.0f); v3 = fmaxf(v3, 0.0f);
            unsigned long long ss01, ss23, cc01, cc23;
            asm("mov.b64 %0, {%1, %2};" : "=l"(ss01) : "f"(s0), "f"(s1));
            asm("mov.b64 %0, {%1, %2};" : "=l"(ss23) : "f"(s2), "f"(s3));
            asm("mov.b64 %0, {%1, %2};" : "=l"(cc01) : "f"(v0), "f"(v1));
            asm("mov.b64 %0, {%1, %2};" : "=l"(cc23) : "f"(v2), "f"(v3));
            int e = (p * 8 + j) * 16;
#pragma unroll
            for (int g = 0; g < NG; g++) {
                ulonglong2 w = wq2[e + g];
                asm("fma.rn.f32x2 %0, %1, %2, %0;" : "+l"(acc[g][0]) : "l"(ss01), "l"(w.x));
                asm("fma.rn.f32x2 %0, %1, %2, %0;" : "+l"(acc[g][1]) : "l"(ss23), "l"(w.x));
                asm("fma.rn.f32x2 %0, %1, %2, %0;" : "+l"(acc[g][0]) : "l"(cc01), "l"(w.y));
                asm("fma.rn.f32x2 %0, %1, %2, %0;" : "+l"(acc[g][1]) : "l"(cc23), "l"(w.y));
            }
        }
    }

    // logits -> dynamic smem; per-thread max in regs
    float mx[NG];
#pragma unroll
    for (int g = 0; g < NG; g++) {
        float a0, a1, a2, a3;
        asm("mov.b64 {%0, %1}, %2;" : "=f"(a0), "=f"(a1) : "l"(acc[g][0]));
        asm("mov.b64 {%0, %1}, %2;" : "=f"(a2), "=f"(a3) : "l"(acc[g][1]));
        float4 sc = *(const float4*)(Sb + (size_t)g * MN + (size_t)r * NCOLS + c0);
        float bg = bp[g];
        float4 o;
        o.x = __logf(fmaxf(a0 + bg, 1e-6f)) + sc.x;
        o.y = __logf(fmaxf(a1 + bg, 1e-6f)) + sc.y;
        o.z = __logf(fmaxf(a2 + bg, 1e-6f)) + sc.z;
        o.w = __logf(fmaxf(a3 + bg, 1e-6f)) + sc.w;
        *(float4*)&sl[g * NCOLS + c0] = o;
        mx[g] = fmaxf(fmaxf(o.x, o.y), fmaxf(o.z, o.w));
    }

    // block max per g
#pragma unroll
    for (int g = 0; g < NG; g++) {
#pragma unroll
        for (int o = 16; o; o >>= 1)
            mx[g] = fmaxf(mx[g], __shfl_xor_sync(0xffffffffu, mx[g], o));
    }
    if (lane == 0) {
#pragma unroll
        for (int g = 0; g < NG; g++) rbuf[g * (NW + 1) + wid] = mx[g];
    }
    __syncthreads();
    if (tid < NG) {
        float t = rbuf[tid * (NW + 1)];
#pragma unroll
        for (int w = 1; w < NW; w++) t = fmaxf(t, rbuf[tid * (NW + 1) + w]);
        rbuf[tid * (NW + 1) + NW] = t;
    }
    __syncthreads();

    // exp + per-thread sum, write exp back to smem
    float sum[NG];
#pragma unroll
    for (int g = 0; g < NG; g++) {
        float m = rbuf[g * (NW + 1) + NW];
        float4 v = *(float4*)&sl[g * NCOLS + c0];
        v.x = __expf(v.x - m); v.y = __expf(v.y - m);
        v.z = __expf(v.z - m); v.w = __expf(v.w - m);
        *(float4*)&sl[g * NCOLS + c0] = v;
        sum[g] = (v.x + v.y) + (v.z + v.w);
    }
    __syncthreads();   // rbuf reuse
#pragma unroll
    for (int g = 0; g < NG; g++) {
#pragma unroll
        for (int o = 16; o; o >>= 1)
            sum[g] += __shfl_xor_sync(0xffffffffu, sum[g], o);
    }
    if (lane == 0) {
#pragma unroll
        for (int g = 0; g < NG; g++) rbuf[g * (NW + 1) + wid] = sum[g];
    }
    __syncthreads();
    if (tid < NG) {
        float t = 0.0f;
#pragma unroll
        for (int w = 0; w < NW; w++) t += rbuf[tid * (NW + 1) + w];
        rbuf[tid * (NW + 1) + NW] = t;
    }
    __syncthreads();

#pragma unroll
    for (int g = 0; g < NG; g++) {
        float inv = __frcp_rn(rbuf[g * (NW + 1) + NW]);
        float4 v = *(float4*)&sl[g * NCOLS + c0];
        v.x *= inv; v.y *= inv; v.z *= inv; v.w *= inv;
        *(float4*)(L + (size_t)g * MN + (size_t)r * NCOLS + c0) = v;
    }
}

// ---------------------------------------------------------------------------
extern "C" void kernel_launch(void* const* d_in, const int* in_sizes, int n_in,
                              void* d_out, int out_size)
{
    (void)in_sizes; (void)n_in; (void)out_size;
    const float* feat      = (const float*)d_in[0];
    const float* ctx_feat  = (const float*)d_in[1];
    const float* box       = (const float*)d_in[2];
    const float* ctx_box   = (const float*)d_in[3];
    const float* w_fc_gt   = (const float*)d_in[4];
    const float* b_fc_gt   = (const float*)d_in[5];
    const float* w_fc_ctx  = (const float*)d_in[6];
    const float* b_fc_ctx  = (const float*)d_in[7];
    const float* w_pos_gt  = (const float*)d_in[8];
    const float* b_pos_gt  = (const float*)d_in[9];
    const float* w_pos_ctx = (const float*)d_in[10];
    const float* b_pos_ctx = (const float*)d_in[11];
    const float* w_conv    = (const float*)d_in[12];
    const float* b_conv    = (const float*)d_in[13];

    float* out = (float*)d_out;
    float* out_gt  = out;
    float* out_ctx = out + (size_t)M_GT * FEAT;

    float *S, *St, *L1, *L2;
    cudaGetSymbolAddress((void**)&S,  g_S);
    cudaGetSymbolAddress((void**)&St, g_St);
    cudaGetSymbolAddress((void**)&L1, g_L1);
    cudaGetSymbolAddress((void**)&L2, g_L2);

    static int attr_done = 0;
    if (!attr_done) {
        cudaFuncSetAttribute(proj_mma, cudaFuncAttributeMaxDynamicSharedMemorySize,
                             2 * PROJ_BUF * 4);
        cudaFuncSetAttribute(attn_mma, cudaFuncAttributeMaxDynamicSharedMemorySize,
                             2 * ATTN_BUF * 4);
        cudaFuncSetAttribute(pos_soft<N_CTX>, cudaFuncAttributeMaxDynamicSharedMemorySize,
                             NG * N_CTX * 4);
        cudaFuncSetAttribute(pos_soft<M_GT>, cudaFuncAttributeMaxDynamicSharedMemorySize,
                             NG * M_GT * 4);
        attr_done = 1;
    }

    // 1) Q, K, Ut, Vt projections (tf32 mma.sync, cp.async pipelined)
    proj_mma<<<dim3(8, 8, 4), 256, 2 * PROJ_BUF * 4>>>(
        feat, ctx_feat, w_fc_gt, b_fc_gt, w_fc_ctx, b_fc_ctx, w_conv);
    // 2) scores S + St
    scores_mma<<<dim3(8, 4, 16), 256>>>();
    // 3) fused pos-embedding + logits + softmax
    pos_soft<N_CTX><<<M_GT, N_CTX / 4, NG * N_CTX * 4>>>(
        (const float4*)box, (const float4*)ctx_box, w_pos_gt, b_pos_gt, S, L1);
    pos_soft<M_GT><<<N_CTX, M_GT / 4, NG * M_GT * 4>>>(
        (const float4*)ctx_box, (const float4*)box, w_pos_ctx, b_pos_ctx, St, L2);
    // 4) attention output (tf32 mma.sync, cp.async pipelined)
    attn_mma<<<dim3(1, 8, 32), 256, 2 * ATTN_BUF * 4>>>(b_conv, out_gt, out_ctx);
}

// round 8
// speedup vs baseline: 2.3102x; 1.0329x over previous
#include <cuda_runtime.h>
#include <cstdint>

#define M_GT  512
#define N_CTX 1024
#define FEAT  1024
#define NG    16
#define DK    64
#define MN    (M_GT * N_CTX)   // 524288

// ---------------- device scratch (static globals; no allocation) ------------
__device__ float g_Q [M_GT * FEAT];
__device__ float g_K [N_CTX * FEAT];
__device__ float g_Ut[FEAT * M_GT];    // Ut[o][m]
__device__ float g_Vt[FEAT * N_CTX];   // Vt[o][n]
__device__ float g_S [NG * MN];        // scores  (G, M, N)
__device__ float g_St[NG * MN];        // scores^T (G, N, M)
__device__ float g_L1[NG * MN];        // weights gt  (G, M, N)
__device__ float g_L2[NG * MN];        // weights ctx (G, N, M)

// 1000^(-j/8)
__constant__ float c_invdim[8] = {
    1.0f, 0.4216965034f, 0.1778279410f, 0.0749894209f,
    0.0316227766f, 0.0133352143f, 0.0056234133f, 0.0023713737f
};

// ======================= helpers ==========================
__device__ __forceinline__ uint32_t f2tf(float x) {
    uint32_t r;
    asm("cvt.rna.tf32.f32 %0, %1;" : "=r"(r) : "f"(x));
    return r;
}

__device__ __forceinline__ void mma8(float* c, const uint32_t* a, const uint32_t* b) {
    asm volatile(
        "mma.sync.aligned.m16n8k8.row.col.f32.tf32.tf32.f32 "
        "{%0,%1,%2,%3}, {%4,%5,%6,%7}, {%8,%9}, {%0,%1,%2,%3};"
        : "+f"(c[0]), "+f"(c[1]), "+f"(c[2]), "+f"(c[3])
        : "r"(a[0]), "r"(a[1]), "r"(a[2]), "r"(a[3]), "r"(b[0]), "r"(b[1]));
}

__device__ __forceinline__ void cp16(uint32_t s, const void* g) {
    asm volatile("cp.async.cg.shared.global [%0], [%1], 16;" :: "r"(s), "l"(g));
}
#define CP_COMMIT() asm volatile("cp.async.commit_group;" ::: "memory")
#define CP_WAIT1()  asm volatile("cp.async.wait_group 1;" ::: "memory")
#define CP_WAIT0()  asm volatile("cp.async.wait_group 0;" ::: "memory")

#define LDP 36   // smem row pitch (floats)

// cp.async issue of a ROWSx32 fp32 chunk into smem [ROWS][LDP] (raw fp32)
template <int ROWS>
__device__ __forceinline__ void issue_chunk(const float* __restrict__ g, int ld,
                                            uint32_t smbase, int tid)
{
#pragma unroll
    for (int i = 0; i < ROWS / 32; i++) {
        int idx = tid + i * 256;
        int r = idx >> 3, c = (idx & 7) << 2;
        cp16(smbase + (uint32_t)(r * LDP + c) * 4u, g + (size_t)r * ld + c);
    }
}

// sync staging with rna cvt (used by scores_mma)
template <int ROWS>
__device__ __forceinline__ void stage(const float* __restrict__ g, int ld,
                                      uint32_t* __restrict__ sm, int tid)
{
#pragma unroll
    for (int i = 0; i < ROWS / 32; i++) {
        int idx = tid + i * 256;
        int r = idx >> 3, c = (idx & 7) << 2;
        float4 v = *(const float4*)(g + (size_t)r * ld + c);
        uint4 t;
        t.x = f2tf(v.x); t.y = f2tf(v.y); t.z = f2tf(v.z); t.w = f2tf(v.w);
        *(uint4*)(sm + r * LDP + c) = t;
    }
}

// ---------------------------------------------------------------------------
// proj_mma: C = A @ W^T (+bias along N). 128x128 tiles, K=1024.
// cp.async double-buffered; cvt.rna at fragment load.
// ---------------------------------------------------------------------------
#define PROJ_BUF (128 * LDP * 2)   // floats per buffer (A tile + B tile)

__global__ __launch_bounds__(256, 2) void proj_mma(
    const float* __restrict__ feat, const float* __restrict__ ctx_feat,
    const float* __restrict__ w_gt, const float* __restrict__ b_gt,
    const float* __restrict__ w_ctx, const float* __restrict__ b_ctx,
    const float* __restrict__ w_conv)
{
    const float* A; const float* W; const float* bias; float* C;
    int Mrows, Ncols;
    switch (blockIdx.z) {
    case 0:  A = feat;   W = w_gt;     bias = b_gt;  C = g_Q;  Mrows = M_GT;  Ncols = FEAT;  break;
    case 1:  A = ctx_feat; W = w_ctx;  bias = b_ctx; C = g_K;  Mrows = N_CTX; Ncols = FEAT;  break;
    case 2:  A = w_conv; W = feat;     bias = 0;     C = g_Ut; Mrows = FEAT;  Ncols = M_GT;  break;
    default: A = w_conv; W = ctx_feat; bias = 0;     C = g_Vt; Mrows = FEAT;  Ncols = N_CTX; break;
    }
    int bm = blockIdx.y * 128, bn = blockIdx.x * 128;
    if (bm >= Mrows || bn >= Ncols) return;

    extern __shared__ float dsm[];
    uint32_t smb = (uint32_t)__cvta_generic_to_shared(dsm);

    int tid = threadIdx.x, wid = tid >> 5, lane = tid & 31;
    int g4 = lane >> 2, tig = lane & 3;
    int wm = (wid & 1) * 64, wn = (wid >> 1) * 32;

    float acc[4][4][4];
#pragma unroll
    for (int i = 0; i < 4; i++)
#pragma unroll
        for (int j = 0; j < 4; j++)
#pragma unroll
            for (int q = 0; q < 4; q++) acc[i][j][q] = 0.0f;

    const float* Ab = A + (size_t)bm * FEAT;
    const float* Wb = W + (size_t)bn * FEAT;

    issue_chunk<128>(Ab, FEAT, smb, tid);
    issue_chunk<128>(Wb, FEAT, smb + 128 * LDP * 4u, tid);
    CP_COMMIT();

    const int NCH = FEAT / 32;
    for (int ch = 0; ch < NCH; ch++) {
        int buf = ch & 1;
        if (ch + 1 < NCH) {
            uint32_t nb = smb + (uint32_t)((ch + 1) & 1) * PROJ_BUF * 4u;
            issue_chunk<128>(Ab + (ch + 1) * 32, FEAT, nb, tid);
            issue_chunk<128>(Wb + (ch + 1) * 32, FEAT, nb + 128 * LDP * 4u, tid);
            CP_COMMIT();
            CP_WAIT1();
        } else {
            CP_WAIT0();
        }
        __syncthreads();
        const float* As = dsm + buf * PROJ_BUF;
        const float* Bs = As + 128 * LDP;
#pragma unroll
        for (int kk = 0; kk < 4; kk++) {
            int k0 = kk * 8 + tig;
            uint32_t bf[4][2];
#pragma unroll
            for (int j = 0; j < 4; j++) {
                int rn = (wn + j * 8 + g4) * LDP;
                bf[j][0] = f2tf(Bs[rn + k0]);
                bf[j][1] = f2tf(Bs[rn + k0 + 4]);
            }
#pragma unroll
            for (int i = 0; i < 4; i++) {
                int r0 = (wm + i * 16 + g4) * LDP;
                uint32_t af[4];
                af[0] = f2tf(As[r0 + k0]);
                af[1] = f2tf(As[r0 + 8 * LDP + k0]);
                af[2] = f2tf(As[r0 + k0 + 4]);
                af[3] = f2tf(As[r0 + 8 * LDP + k0 + 4]);
#pragma unroll
                for (int j = 0; j < 4; j++) mma8(acc[i][j], af, bf[j]);
            }
        }
        __syncthreads();
    }

#pragma unroll
    for (int i = 0; i < 4; i++) {
        int row = bm + wm + i * 16 + g4;
#pragma unroll
        for (int j = 0; j < 4; j++) {
            int col = bn + wn + j * 8 + 2 * tig;
            float b0 = bias ? bias[col] : 0.0f;
            float b1 = bias ? bias[col + 1] : 0.0f;
            float2 o0, o1;
            o0.x = acc[i][j][0] + b0; o0.y = acc[i][j][1] + b1;
            o1.x = acc[i][j][2] + b0; o1.y = acc[i][j][3] + b1;
            *(float2*)(C + (size_t)row * Ncols + col)       = o0;
            *(float2*)(C + (size_t)(row + 8) * Ncols + col) = o1;
        }
    }
}

// ---------------------------------------------------------------------------
// scores_mma: S[g,m,n] = 0.125 * Q.K ; St[g,n,m] via smem transpose.
// ---------------------------------------------------------------------------
#define TP 68   // transpose pitch (floats): 16B-aligned, conflict-free STS

__global__ __launch_bounds__(256, 2) void scores_mma()
{
    int g = blockIdx.z;
    int bm = blockIdx.y * 128, bn = blockIdx.x * 128;
    const float* A = g_Q + (size_t)bm * FEAT + g * DK;
    const float* B = g_K + (size_t)bn * FEAT + g * DK;
    float* C  = g_S  + (size_t)g * MN;
    float* Ct = g_St + (size_t)g * MN;

    // shared buffer reused: mainloop tiles (2*128*LDP u32 = 36864B),
    // then transpose buffer (128*TP floats = 34816B)
    __shared__ __align__(16) uint32_t sbuf[2 * 128 * LDP];
    uint32_t* As = sbuf;
    uint32_t* Bs = sbuf + 128 * LDP;
    float* T = (float*)sbuf;

    int tid = threadIdx.x, wid = tid >> 5, lane = tid & 31;
    int g4 = lane >> 2, tig = lane & 3;
    int wm = (wid & 1) * 64, wn = (wid >> 1) * 32;

    float acc[4][4][4];
#pragma unroll
    for (int i = 0; i < 4; i++)
#pragma unroll
        for (int j = 0; j < 4; j++)
#pragma unroll
            for (int q = 0; q < 4; q++) acc[i][j][q] = 0.0f;

    for (int ch = 0; ch < 2; ch++) {
        stage<128>(A + ch * 32, FEAT, As, tid);
        stage<128>(B + ch * 32, FEAT, Bs, tid);
        __syncthreads();
#pragma unroll
        for (int kk = 0; kk < 4; kk++) {
            int k0 = kk * 8 + tig;
            uint32_t bf[4][2];
#pragma unroll
            for (int j = 0; j < 4; j++) {
                int rn = (wn + j * 8 + g4) * LDP;
                bf[j][0] = Bs[rn + k0];
                bf[j][1] = Bs[rn + k0 + 4];
            }
#pragma unroll
            for (int i = 0; i < 4; i++) {
                int r0 = (wm + i * 16 + g4) * LDP;
                uint32_t af[4];
                af[0] = As[r0 + k0];
                af[1] = As[r0 + 8 * LDP + k0];
                af[2] = As[r0 + k0 + 4];
                af[3] = As[r0 + 8 * LDP + k0 + 4];
#pragma unroll
                for (int j = 0; j < 4; j++) mma8(acc[i][j], af, bf[j]);
            }
        }
        __syncthreads();
    }

    // normal S store (coalesced)
#pragma unroll
    for (int i = 0; i < 4; i++) {
        int row = bm + wm + i * 16 + g4;
#pragma unroll
        for (int j = 0; j < 4; j++) {
            int col = bn + wn + j * 8 + 2 * tig;
            float2 o0, o1;
            o0.x = acc[i][j][0] * 0.125f; o0.y = acc[i][j][1] * 0.125f;
            o1.x = acc[i][j][2] * 0.125f; o1.y = acc[i][j][3] * 0.125f;
            *(float2*)(C + (size_t)row * N_CTX + col)       = o0;
            *(float2*)(C + (size_t)(row + 8) * N_CTX + col) = o1;
        }
    }

    // St store via smem transpose: two 64-row halves (warp-row h owns half h)
    for (int hh = 0; hh < 2; hh++) {
        __syncthreads();
        if ((wid & 1) == hh) {
#pragma unroll
            for (int i = 0; i < 4; i++) {
                int rl = i * 16 + g4;   // local row within this half
#pragma unroll
                for (int j = 0; j < 4; j++) {
                    int col = wn + j * 8 + 2 * tig;
                    T[col * TP + rl]            = acc[i][j][0] * 0.125f;
                    T[(col + 1) * TP + rl]      = acc[i][j][1] * 0.125f;
                    T[col * TP + rl + 8]        = acc[i][j][2] * 0.125f;
                    T[(col + 1) * TP + rl + 8]  = acc[i][j][3] * 0.125f;
                }
            }
        }
        __syncthreads();
        // coalesced write-out: thread -> (col, 32-elem segment)
        int col = tid >> 1, seg = (tid & 1) << 5;
        const float* src = T + col * TP + seg;
        float* dst = Ct + (size_t)(bn + col) * M_GT + bm + hh * 64 + seg;
#pragma unroll
        for (int k = 0; k < 8; k++)
            *(float4*)(dst + k * 4) = *(const float4*)(src + k * 4);
    }
}

// ---------------------------------------------------------------------------
// attn_mma: z 0..15 gt, z 16..31 ctx. 128x64 tiles, warp tile 64x16.
// ---------------------------------------------------------------------------
#define ATTN_BUF (128 * LDP + 64 * LDP)   // floats per buffer

__global__ __launch_bounds__(256, 2) void attn_mma(
    const float* __restrict__ b_conv, float* __restrict__ out_gt,
    float* __restrict__ out_ctx)
{
    int z = blockIdx.z;
    int g = z & 15;
    bool gt = z < 16;
    const float* A = gt ? g_L1 + (size_t)g * MN : g_L2 + (size_t)g * MN;
    const float* B = gt ? g_Vt + (size_t)(g * DK) * N_CTX
                        : g_Ut + (size_t)(g * DK) * M_GT;
    float* C  = gt ? out_gt : out_ctx;
    int Mrows = gt ? M_GT : N_CTX;
    int Ktot  = gt ? N_CTX : M_GT;
    int bm = blockIdx.y * 128;
    if (bm >= Mrows) return;

    extern __shared__ float dsm[];
    uint32_t smb = (uint32_t)__cvta_generic_to_shared(dsm);

    int tid = threadIdx.x, wid = tid >> 5, lane = tid & 31;
    int g4 = lane >> 2, tig = lane & 3;
    int wm = (wid & 1) * 64, wn = (wid >> 1) * 16;

    float acc[4][2][4];
#pragma unroll
    for (int i = 0; i < 4; i++)
#pragma unroll
        for (int j = 0; j < 2; j++)
#pragma unroll
            for (int q = 0; q < 4; q++) acc[i][j][q] = 0.0f;

    const float* Ab = A + (size_t)bm * Ktot;

    issue_chunk<128>(Ab, Ktot, smb, tid);
    issue_chunk<64>(B, Ktot, smb + 128 * LDP * 4u, tid);
    CP_COMMIT();

    int NCH = Ktot / 32;
    for (int ch = 0; ch < NCH; ch++) {
        int buf = ch & 1;
        if (ch + 1 < NCH) {
            uint32_t nb = smb + (uint32_t)((ch + 1) & 1) * ATTN_BUF * 4u;
            issue_chunk<128>(Ab + (ch + 1) * 32, Ktot, nb, tid);
            issue_chunk<64>(B + (ch + 1) * 32, Ktot, nb + 128 * LDP * 4u, tid);
            CP_COMMIT();
            CP_WAIT1();
        } else {
            CP_WAIT0();
        }
        __syncthreads();
        const float* As = dsm + buf * ATTN_BUF;
        const float* Bs = As + 128 * LDP;
#pragma unroll
        for (int kk = 0; kk < 4; kk++) {
            int k0 = kk * 8 + tig;
            uint32_t bf[2][2];
#pragma unroll
            for (int j = 0; j < 2; j++) {
                int rn = (wn + j * 8 + g4) * LDP;
                bf[j][0] = f2tf(Bs[rn + k0]);
                bf[j][1] = f2tf(Bs[rn + k0 + 4]);
            }
#pragma unroll
            for (int i = 0; i < 4; i++) {
                int r0 = (wm + i * 16 + g4) * LDP;
                uint32_t af[4];
                af[0] = f2tf(As[r0 + k0]);
                af[1] = f2tf(As[r0 + 8 * LDP + k0]);
                af[2] = f2tf(As[r0 + k0 + 4]);
                af[3] = f2tf(As[r0 + 8 * LDP + k0 + 4]);
#pragma unroll
                for (int j = 0; j < 2; j++) mma8(acc[i][j], af, bf[j]);
            }
        }
        __syncthreads();
    }

#pragma unroll
    for (int i = 0; i < 4; i++) {
        int row = bm + wm + i * 16 + g4;
#pragma unroll
        for (int j = 0; j < 2; j++) {
            int col = g * DK + wn + j * 8 + 2 * tig;
            float b0 = b_conv[col], b1 = b_conv[col + 1];
            float2 o0, o1;
            o0.x = acc[i][j][0] + b0; o0.y = acc[i][j][1] + b1;
            o1.x = acc[i][j][2] + b0; o1.y = acc[i][j][3] + b1;
            *(float2*)(C + (size_t)row * FEAT + col)       = o0;
            *(float2*)(C + (size_t)(row + 8) * FEAT + col) = o1;
        }
    }
}

// ---------------------------------------------------------------------------
// pos_soft<NCOLS>: fused pos-embedding + logit + row softmax.
// One block per row; NCOLS/4 threads, 4 columns/thread.
// __launch_bounds__ minBlocks caps regs at 128 -> 16 warps/SM (25% occ).
// ---------------------------------------------------------------------------
template <int NCOLS>
__global__ __launch_bounds__(NCOLS / 4, 512 / (NCOLS / 4)) void pos_soft(
    const float4* __restrict__ boxA, const float4* __restrict__ boxB,
    const float* __restrict__ w_pos, const float* __restrict__ b_pos,
    const float* __restrict__ Sb, float* __restrict__ L)
{
    constexpr int NT = NCOLS / 4;
    constexpr int NW = NT / 32;
    extern __shared__ float sl[];                 // [NG][NCOLS] logits
    __shared__ __align__(16) float wq[512 * 4];   // [(p*8+j)*16+g] = {ws,ws,wc,wc}
    __shared__ float bp[NG];
    __shared__ float rbuf[NG * (NW + 1)];

    int tid = threadIdx.x, wid = tid >> 5, lane = tid & 31;
    for (int i = tid; i < 512; i += NT) {
        int pj = i >> 4, g = i & 15;
        int p = pj >> 3, j = pj & 7;
        float ws = w_pos[g * 64 + p * 16 + j];
        float wc = w_pos[g * 64 + p * 16 + 8 + j];
        wq[i * 4 + 0] = ws; wq[i * 4 + 1] = ws;
        wq[i * 4 + 2] = wc; wq[i * 4 + 3] = wc;
    }
    if (tid < NG) bp[tid] = b_pos[tid];
    __syncthreads();

    int r = blockIdx.x;
    int c0 = tid * 4;

    float4 A = boxA[r];
    float bw = A.z - A.x + 1.0f, bh = A.w - A.y + 1.0f;
    float cx = 0.5f * (A.x + A.z), cy = 0.5f * (A.y + A.w);

    float pp[4][4];
#pragma unroll
    for (int q = 0; q < 4; q++) {
        float4 Bx = boxB[c0 + q];
        pp[q][0] = __logf(fmaxf(fabsf((cx - 0.5f * (Bx.x + Bx.z)) / bw), 1e-3f));
        pp[q][1] = __logf(fmaxf(fabsf((cy - 0.5f * (Bx.y + Bx.w)) / bh), 1e-3f));
        pp[q][2] = __logf((Bx.z - Bx.x + 1.0f) / bw);
        pp[q][3] = __logf((Bx.w - Bx.y + 1.0f) / bh);
    }

    unsigned long long acc[NG][2];
#pragma unroll
    for (int g = 0; g < NG; g++) { acc[g][0] = 0ull; acc[g][1] = 0ull; }

    const ulonglong2* wq2 = (const ulonglong2*)wq;
#pragma unroll
    for (int p = 0; p < 4; p++) {
        float b0 = 100.0f * pp[0][p], b1 = 100.0f * pp[1][p];
        float b2 = 100.0f * pp[2][p], b3 = 100.0f * pp[3][p];
#pragma unroll
        for (int j = 0; j < 8; j++) {
            float iv = c_invdim[j];
            float s0, v0, s1, v1, s2, v2, s3, v3;
            __sincosf(b0 * iv, &s0, &v0);
            __sincosf(b1 * iv, &s1, &v1);
            __sincosf(b2 * iv, &s2, &v2);
            __sincosf(b3 * iv, &s3, &v3);
            s0 = fmaxf(s0, 0.0f); s1 = fmaxf(s1, 0.0f);
            s2 = fmaxf(s2, 0.0f); s3 = fmaxf(s3, 0.0f);
            v0 = fmaxf(v0, 0.0f); v1 = fmaxf(v1, 0.0f);
            v2 = fmaxf(v2, 0.0f); v3 = fmaxf(v3, 0.0f);
            unsigned long long ss01, ss23, cc01, cc23;
            asm("mov.b64 %0, {%1, %2};" : "=l"(ss01) : "f"(s0), "f"(s1));
            asm("mov.b64 %0, {%1, %2};" : "=l"(ss23) : "f"(s2), "f"(s3));
            asm("mov.b64 %0, {%1, %2};" : "=l"(cc01) : "f"(v0), "f"(v1));
            asm("mov.b64 %0, {%1, %2};" : "=l"(cc23) : "f"(v2), "f"(v3));
            int e = (p * 8 + j) * 16;
#pragma unroll
            for (int g = 0; g < NG; g++) {
                ulonglong2 w = wq2[e + g];
                asm("fma.rn.f32x2 %0, %1, %2, %0;" : "+l"(acc[g][0]) : "l"(ss01), "l"(w.x));
                asm("fma.rn.f32x2 %0, %1, %2, %0;" : "+l"(acc[g][1]) : "l"(ss23), "l"(w.x));
                asm("fma.rn.f32x2 %0, %1, %2, %0;" : "+l"(acc[g][0]) : "l"(cc01), "l"(w.y));
                asm("fma.rn.f32x2 %0, %1, %2, %0;" : "+l"(acc[g][1]) : "l"(cc23), "l"(w.y));
            }
        }
    }

    // logits -> dynamic smem; per-thread max in regs
    float mx[NG];
#pragma unroll
    for (int g = 0; g < NG; g++) {
        float a0, a1, a2, a3;
        asm("mov.b64 {%0, %1}, %2;" : "=f"(a0), "=f"(a1) : "l"(acc[g][0]));
        asm("mov.b64 {%0, %1}, %2;" : "=f"(a2), "=f"(a3) : "l"(acc[g][1]));
        float4 sc = *(const float4*)(Sb + (size_t)g * MN + (size_t)r * NCOLS + c0);
        float bg = bp[g];
        float4 o;
        o.x = __logf(fmaxf(a0 + bg, 1e-6f)) + sc.x;
        o.y = __logf(fmaxf(a1 + bg, 1e-6f)) + sc.y;
        o.z = __logf(fmaxf(a2 + bg, 1e-6f)) + sc.z;
        o.w = __logf(fmaxf(a3 + bg, 1e-6f)) + sc.w;
        *(float4*)&sl[g * NCOLS + c0] = o;
        mx[g] = fmaxf(fmaxf(o.x, o.y), fmaxf(o.z, o.w));
    }

    // block max per g
#pragma unroll
    for (int g = 0; g < NG; g++) {
#pragma unroll
        for (int o = 16; o; o >>= 1)
            mx[g] = fmaxf(mx[g], __shfl_xor_sync(0xffffffffu, mx[g], o));
    }
    if (lane == 0) {
#pragma unroll
        for (int g = 0; g < NG; g++) rbuf[g * (NW + 1) + wid] = mx[g];
    }
    __syncthreads();
    if (tid < NG) {
        float t = rbuf[tid * (NW + 1)];
#pragma unroll
        for (int w = 1; w < NW; w++) t = fmaxf(t, rbuf[tid * (NW + 1) + w]);
        rbuf[tid * (NW + 1) + NW] = t;
    }
    __syncthreads();

    // exp + per-thread sum
    float sum[NG];
#pragma unroll
    for (int g = 0; g < NG; g++) {
        float m = rbuf[g * (NW + 1) + NW];
        float4 v = *(float4*)&sl[g * NCOLS + c0];
        v.x = __expf(v.x - m); v.y = __expf(v.y - m);
        v.z = __expf(v.z - m); v.w = __expf(v.w - m);
        *(float4*)&sl[g * NCOLS + c0] = v;
        sum[g] = (v.x + v.y) + (v.z + v.w);
    }
    __syncthreads();   // rbuf reuse
#pragma unroll
    for (int g = 0; g < NG; g++) {
#pragma unroll
        for (int o = 16; o; o >>= 1)
            sum[g] += __shfl_xor_sync(0xffffffffu, sum[g], o);
    }
    if (lane == 0) {
#pragma unroll
        for (int g = 0; g < NG; g++) rbuf[g * (NW + 1) + wid] = sum[g];
    }
    __syncthreads();
    if (tid < NG) {
        float t = 0.0f;
#pragma unroll
        for (int w = 0; w < NW; w++) t += rbuf[tid * (NW + 1) + w];
        rbuf[tid * (NW + 1) + NW] = t;
    }
    __syncthreads();

#pragma unroll
    for (int g = 0; g < NG; g++) {
        float inv = __frcp_rn(rbuf[g * (NW + 1) + NW]);
        float4 v = *(float4*)&sl[g * NCOLS + c0];
        v.x *= inv; v.y *= inv; v.z *= inv; v.w *= inv;
        *(float4*)(L + (size_t)g * MN + (size_t)r * NCOLS + c0) = v;
    }
}

// ---------------------------------------------------------------------------
extern "C" void kernel_launch(void* const* d_in, const int* in_sizes, int n_in,
                              void* d_out, int out_size)
{
    (void)in_sizes; (void)n_in; (void)out_size;
    const float* feat      = (const float*)d_in[0];
    const float* ctx_feat  = (const float*)d_in[1];
    const float* box       = (const float*)d_in[2];
    const float* ctx_box   = (const float*)d_in[3];
    const float* w_fc_gt   = (const float*)d_in[4];
    const float* b_fc_gt   = (const float*)d_in[5];
    const float* w_fc_ctx  = (const float*)d_in[6];
    const float* b_fc_ctx  = (const float*)d_in[7];
    const float* w_pos_gt  = (const float*)d_in[8];
    const float* b_pos_gt  = (const float*)d_in[9];
    const float* w_pos_ctx = (const float*)d_in[10];
    const float* b_pos_ctx = (const float*)d_in[11];
    const float* w_conv    = (const float*)d_in[12];
    const float* b_conv    = (const float*)d_in[13];

    float* out = (float*)d_out;
    float* out_gt  = out;
    float* out_ctx = out + (size_t)M_GT * FEAT;

    float *S, *St, *L1, *L2;
    cudaGetSymbolAddress((void**)&S,  g_S);
    cudaGetSymbolAddress((void**)&St, g_St);
    cudaGetSymbolAddress((void**)&L1, g_L1);
    cudaGetSymbolAddress((void**)&L2, g_L2);

    static int attr_done = 0;
    if (!attr_done) {
        cudaFuncSetAttribute(proj_mma, cudaFuncAttributeMaxDynamicSharedMemorySize,
                             2 * PROJ_BUF * 4);
        cudaFuncSetAttribute(attn_mma, cudaFuncAttributeMaxDynamicSharedMemorySize,
                             2 * ATTN_BUF * 4);
        cudaFuncSetAttribute(pos_soft<N_CTX>, cudaFuncAttributeMaxDynamicSharedMemorySize,
                             NG * N_CTX * 4);
        cudaFuncSetAttribute(pos_soft<M_GT>, cudaFuncAttributeMaxDynamicSharedMemorySize,
                             NG * M_GT * 4);
        attr_done = 1;
    }

    // 1) Q, K, Ut, Vt projections (tf32 mma.sync, cp.async pipelined)
    proj_mma<<<dim3(8, 8, 4), 256, 2 * PROJ_BUF * 4>>>(
        feat, ctx_feat, w_fc_gt, b_fc_gt, w_fc_ctx, b_fc_ctx, w_conv);
    // 2) scores S + St (smem-transposed St store)
    scores_mma<<<dim3(8, 4, 16), 256>>>();
    // 3) fused pos-embedding + logits + softmax
    pos_soft<N_CTX><<<M_GT, N_CTX / 4, NG * N_CTX * 4>>>(
        (const float4*)box, (const float4*)ctx_box, w_pos_gt, b_pos_gt, S, L1);
    pos_soft<M_GT><<<N_CTX, M_GT / 4, NG * M_GT * 4>>>(
        (const float4*)ctx_box, (const float4*)box, w_pos_ctx, b_pos_ctx, St, L2);
    // 4) attention output (tf32 mma.sync, cp.async pipelined)
    attn_mma<<<dim3(1, 8, 32), 256, 2 * ATTN_BUF * 4>>>(b_conv, out_gt, out_ctx);
}